// round 9
// baseline (speedup 1.0000x reference)
#include <cuda_runtime.h>
#include <cuda_bf16.h>
#include <math.h>
#include <stdint.h>

#define BATCH   128
#define SEQ     512
#define INPUT   512
#define HIDDEN  1024
#define OUTPUT  256
#define NBLK    128
#define JW      32
#define MW      32

__device__ float          g_xin[(size_t)SEQ * BATCH * HIDDEN];
__device__ float          g_hf[BATCH * HIDDEN];
__device__ __nv_bfloat16  g_hhi[3][BATCH * HIDDEN];
__device__ __nv_bfloat16  g_hlo[3][BATCH * HIDDEN];
__device__ __nv_bfloat16  g_xhi[(size_t)BATCH * SEQ * INPUT];
__device__ __nv_bfloat16  g_xlo[(size_t)BATCH * SEQ * INPUT];
__device__ __nv_bfloat16  g_wThi[HIDDEN * INPUT];
__device__ __nv_bfloat16  g_wTlo[HIDDEN * INPUT];
__device__ unsigned g_flags[NBLK * 32];    // 128B-strided per-block step flags
__device__ unsigned g_bar_cnt;
__device__ unsigned g_bar_gen;

#define OFF_WHI    0
#define OFF_WLO    65536
#define OFF_STAGE  131072
#define OFF_RED    OFF_STAGE
#define OFF_BH     229376
#define OFF_ITAU   229504
#define OFF_GEN0   229632
#define SCAN_SMEM  229696

#define OFF_GA     0
#define OFF_GB     98304
#define OFF_BIN    147456
#define GEMM_SMEM  147968

__device__ __forceinline__ uint32_t smem_u32(const void* p) {
    uint32_t a;
    asm("{ .reg .u64 t; cvta.to.shared.u64 t, %1; cvt.u32.u64 %0, t; }" : "=r"(a) : "l"(p));
    return a;
}
#define CP_COMMIT() asm volatile("cp.async.commit_group;" ::: "memory")
#define CP_WAIT1()  asm volatile("cp.async.wait_group 1;" ::: "memory")
#define CP_WAIT0()  asm volatile("cp.async.wait_group 0;" ::: "memory")

__device__ __forceinline__ void cp16(uint32_t dst, const void* src) {
    asm volatile("cp.async.cg.shared.global [%0], [%1], 16;" :: "r"(dst), "l"(src) : "memory");
}
__device__ __forceinline__ void ldsm4(uint32_t& r0, uint32_t& r1, uint32_t& r2, uint32_t& r3,
                                      uint32_t a) {
    asm volatile("ldmatrix.sync.aligned.m8n8.x4.shared.b16 {%0,%1,%2,%3}, [%4];"
                 : "=r"(r0), "=r"(r1), "=r"(r2), "=r"(r3) : "r"(a));
}
__device__ __forceinline__ void mma16816(float* d, const uint32_t* a, uint32_t b0, uint32_t b1) {
    asm volatile("mma.sync.aligned.m16n8k16.row.col.f32.bf16.bf16.f32 "
                 "{%0,%1,%2,%3}, {%4,%5,%6,%7}, {%8,%9}, {%0,%1,%2,%3};"
                 : "+f"(d[0]), "+f"(d[1]), "+f"(d[2]), "+f"(d[3])
                 : "r"(a[0]), "r"(a[1]), "r"(a[2]), "r"(a[3]), "r"(b0), "r"(b1));
}
__device__ __forceinline__ uint32_t pbf2(float a, float b) {
    __nv_bfloat162 t = __floats2bfloat162_rn(a, b);
    return *(uint32_t*)&t;
}
__device__ __forceinline__ void grid_sync(unsigned target)
{
    __threadfence();
    __syncthreads();
    if (threadIdx.x == 0) {
        unsigned arrived = atomicAdd(&g_bar_cnt, 1u);
        if (arrived == NBLK - 1) {
            atomicExch(&g_bar_cnt, 0u);
            __threadfence();
            atomicAdd(&g_bar_gen, 1u);
        } else {
            while ((int)(*(volatile unsigned*)&g_bar_gen - target) < 0) { }
            __threadfence();
        }
    }
    __syncthreads();
}

__global__ __launch_bounds__(256) void conv_x_kernel(const float* __restrict__ x)
{
    const size_t total = (size_t)BATCH * SEQ * INPUT / 2;
    size_t base = (size_t)blockIdx.x * 256 + threadIdx.x;
    size_t stride = (size_t)gridDim.x * 256;
    uint32_t* xhi = (uint32_t*)g_xhi;
    uint32_t* xlo = (uint32_t*)g_xlo;
    for (size_t p = base; p < total; p += stride) {
        float2 v = ((const float2*)x)[p];
        uint32_t hp = pbf2(v.x, v.y);
        __nv_bfloat162 hb = *(__nv_bfloat162*)&hp;
        xhi[p] = hp;
        xlo[p] = pbf2(v.x - __bfloat162float(hb.x), v.y - __bfloat162float(hb.y));
    }
}

__global__ __launch_bounds__(256) void conv_w_kernel(const float* __restrict__ Win)
{
    int idx = blockIdx.x * 256 + threadIdx.x;
    if (idx >= INPUT * HIDDEN) return;
    int k = idx >> 10, n = idx & 1023;
    float w = Win[idx];
    __nv_bfloat16 whi = __float2bfloat16(w);
    g_wThi[(size_t)n * INPUT + k] = whi;
    g_wTlo[(size_t)n * INPUT + k] = __float2bfloat16(w - __bfloat162float(whi));
}

// ---------------- Phase 1 GEMM (unchanged) ----------------
__device__ __forceinline__ void gstage(uint32_t sb, int kc, int m0, int n0, int tid)
{
    uint32_t abase = sb + OFF_GA + (uint32_t)(kc % 3) * 32768u;
    uint32_t bbase = sb + OFF_GB + (uint32_t)(kc % 3) * 16384u;
#pragma unroll
    for (int u = 0; u < 8; ++u) {
        int g = tid + u * 256;
        int seg = g & 7, row = (g >> 3) & 127, plane = g >> 10;
        const char* src = (const char*)(plane ? g_xlo : g_xhi)
                        + (size_t)(m0 + row) * 1024 + (size_t)kc * 128 + seg * 16;
        cp16(abase + plane * 16384 + row * 128 + ((seg * 16) ^ ((row & 7) << 4)), src);
    }
#pragma unroll
    for (int u = 0; u < 4; ++u) {
        int g = tid + u * 256;
        int seg = g & 7, row = (g >> 3) & 63, plane = g >> 9;
        const char* src = (const char*)(plane ? g_wTlo : g_wThi)
                        + (size_t)(n0 + row) * 1024 + (size_t)kc * 128 + seg * 16;
        cp16(bbase + plane * 8192 + row * 128 + ((seg * 16) ^ ((row & 7) << 4)), src);
    }
}

__global__ __launch_bounds__(256, 1) void gemm_xin_mma(const float* __restrict__ bin)
{
    extern __shared__ __align__(1024) char smem[];
    const uint32_t sb = smem_u32(smem);
    const int tid = threadIdx.x, wid = tid >> 5, lid = tid & 31;
    const int n0 = blockIdx.x * 64, m0 = blockIdx.y * 128;
    const int mq = wid & 3, nh = wid >> 2;
    float* bin_s = (float*)(smem + OFF_BIN);
    if (tid < 16) ((float4*)bin_s)[tid] = ((const float4*)(bin + n0))[tid];

    const int grp = lid >> 3;
    int a_rowl[2];
    a_rowl[0] = mq * 32 + (lid & 7) + ((grp & 1) << 3);
    a_rowl[1] = a_rowl[0] + 16;
    const int a_koff = (grp >> 1) << 4;
    const int b_nr   = nh * 32 + (lid & 7) + ((grp >> 1) << 3);
    const int b_koff = (grp & 1) << 4;
    const uint32_t b_xor = (uint32_t)((b_nr & 7) << 4);

    float acc[2][4][4];
#pragma unroll
    for (int i = 0; i < 2; ++i)
#pragma unroll
        for (int j = 0; j < 4; ++j)
#pragma unroll
            for (int r = 0; r < 4; ++r) acc[i][j][r] = 0.0f;

    gstage(sb, 0, m0, n0, tid); CP_COMMIT();
    gstage(sb, 1, m0, n0, tid); CP_COMMIT();

    for (int kc = 0; kc < 8; ++kc) {
        CP_WAIT1();
        __syncthreads();
        if (kc + 2 < 8) gstage(sb, kc + 2, m0, n0, tid);
        CP_COMMIT();
        const uint32_t abase = sb + OFF_GA + (uint32_t)(kc % 3) * 32768u;
        const uint32_t bbase = sb + OFF_GB + (uint32_t)(kc % 3) * 16384u;
#pragma unroll
        for (int k2 = 0; k2 < 4; ++k2) {
            const uint32_t kb = (uint32_t)(k2 * 32);
            uint32_t ahi[2][4], alo[2][4];
#pragma unroll
            for (int mt = 0; mt < 2; ++mt) {
                uint32_t aa = abase + (uint32_t)(a_rowl[mt] * 128)
                            + ((kb + a_koff) ^ ((a_rowl[mt] & 7) << 4));
                ldsm4(ahi[mt][0], ahi[mt][1], ahi[mt][2], ahi[mt][3], aa);
                ldsm4(alo[mt][0], alo[mt][1], alo[mt][2], alo[mt][3], aa + 16384);
            }
            uint32_t bhi[8], blo[8];
            {
                uint32_t ba = bbase + (uint32_t)(b_nr * 128) + ((kb + b_koff) ^ b_xor);
                ldsm4(bhi[0], bhi[1], bhi[2], bhi[3], ba);
                ldsm4(bhi[4], bhi[5], bhi[6], bhi[7], ba + 2048);
                ldsm4(blo[0], blo[1], blo[2], blo[3], ba + 8192);
                ldsm4(blo[4], blo[5], blo[6], blo[7], ba + 8192 + 2048);
            }
#pragma unroll
            for (int mt = 0; mt < 2; ++mt)
#pragma unroll
                for (int j = 0; j < 4; ++j) {
                    mma16816(acc[mt][j], ahi[mt], bhi[j * 2], bhi[j * 2 + 1]);
                    mma16816(acc[mt][j], alo[mt], bhi[j * 2], bhi[j * 2 + 1]);
                    mma16816(acc[mt][j], ahi[mt], blo[j * 2], blo[j * 2 + 1]);
                }
        }
    }

    const int er = lid >> 2, ec = (lid & 3) * 2;
#pragma unroll
    for (int mt = 0; mt < 2; ++mt)
#pragma unroll
        for (int rt = 0; rt < 2; ++rt) {
            int m = m0 + mq * 32 + mt * 16 + er + rt * 8;
            int b = m >> 9, s = m & 511;
            float* orow = g_xin + ((size_t)s * BATCH + b) * HIDDEN + n0;
#pragma unroll
            for (int j = 0; j < 4; ++j) {
                int nl = nh * 32 + j * 8 + ec;
                float2 v;
                v.x = acc[mt][j][rt * 2 + 0] + bin_s[nl];
                v.y = acc[mt][j][rt * 2 + 1] + bin_s[nl + 1];
                *(float2*)(orow + nl) = v;
            }
        }
}

// ---------------- Scan: flags instead of barrier ----------------
__device__ __forceinline__ void stage_quad(uint32_t sb, const __nv_bfloat16* hi,
                                           const __nv_bfloat16* lo, int i, int m0, int tid)
{
    uint32_t base = sb + OFF_STAGE + (uint32_t)(i % 3) * 32768u;
#pragma unroll
    for (int u = 0; u < 4; ++u) {
        int g = tid + u * 512;
        int seg = g & 7, row = (g >> 3) & 31, plane = (g >> 8) & 1, kg = g >> 9;
        int c = kg * 4 + i;
        const char* src = (const char*)(plane ? lo : hi)
                        + (size_t)(m0 + row) * 2048 + (size_t)c * 128 + seg * 16;
        cp16(base + kg * 8192 + plane * 4096 + row * 128 + ((seg * 16) ^ ((row & 7) << 4)), src);
    }
}

// poll producers of stage-iteration i (chunks kg*4+i): jt = 8g + 2i + p
__device__ __forceinline__ void poll_stage(int mt, int i, unsigned need, int tid)
{
    if (tid < 8) {
        int jt = 8 * (tid >> 1) + 2 * i + (tid & 1);
        volatile unsigned* f = &g_flags[(mt * 32 + jt) * 32];
        while ((int)(*f - need) < 0) { }
    }
}

__global__ __launch_bounds__(512, 1) void scan_mma_kernel(
    const float* __restrict__ Wh,  const float* __restrict__ bh,
    const float* __restrict__ tau, const float* __restrict__ Wout,
    const float* __restrict__ bout, float* __restrict__ out)
{
    extern __shared__ __align__(1024) char smem[];
    const uint32_t sb = smem_u32(smem);
    const int tid = threadIdx.x, wid = tid >> 5, lid = tid & 31;
    const int jt = blockIdx.x >> 2, mt_blk = blockIdx.x & 3;
    const int j0 = jt * JW, m0 = mt_blk * MW;
    const int me = (mt_blk * 32 + jt) * 32;
    float* bh_s   = (float*)(smem + OFF_BH);
    float* itau_s = (float*)(smem + OFF_ITAU);
    float* red    = (float*)(smem + OFF_RED);

    if (tid == 0) {
        ((unsigned*)(smem + OFF_GEN0))[0] = *(volatile unsigned*)&g_bar_gen;
        ((unsigned*)(smem + OFF_GEN0))[1] = *(volatile unsigned*)&g_flags[me];
    }
    if (tid < JW) {
        bh_s[tid]   = bh[j0 + tid];
        itau_s[tid] = 1.0f / tau[j0 + tid];
    }

    for (int idx = tid; idx < 1024 * 8; idx += 512) {
        int k = idx >> 3, nq = idx & 7;
        float4 wv = *(const float4*)(Wh + (size_t)k * HIDDEN + j0 + nq * 4);
        float w[4] = {wv.x, wv.y, wv.z, wv.w};
#pragma unroll
        for (int e = 0; e < 4; ++e) {
            int n = nq * 4 + e;
            uint32_t so = (uint32_t)((k >> 6) * 4096 + n * 128)
                        + (uint32_t)((((k & 63) * 2) ^ ((n & 7) << 4)));
            __nv_bfloat16 whi = __float2bfloat16(w[e]);
            *(__nv_bfloat16*)(smem + OFF_WHI + so) = whi;
            *(__nv_bfloat16*)(smem + OFF_WLO + so) =
                __float2bfloat16(w[e] - __bfloat162float(whi));
        }
    }
    for (int idx = tid; idx < MW * JW / 2; idx += 512) {
        int r = idx / (JW / 2), c = idx % (JW / 2);
        size_t o = (size_t)(m0 + r) * HIDDEN + j0 + c * 2;
        *(uint32_t*)(g_hhi[0] + o) = 0u;
        *(uint32_t*)(g_hlo[0] + o) = 0u;
    }
    __syncthreads();
    const unsigned gen0 = ((unsigned*)(smem + OFF_GEN0))[0];
    const unsigned B0   = ((unsigned*)(smem + OFF_GEN0))[1];

    grid_sync(gen0 + 1);   // h0 visible everywhere; flags all == B0

    const int w_mt = wid & 1, w_nh = (wid >> 1) & 1, kg = wid >> 2;
    const int grp = lid >> 3;
    const int a_row  = w_mt * 16 + (lid & 7) + ((grp & 1) << 3);
    const int a_koff = (grp >> 1) << 4;
    const uint32_t a_off = (uint32_t)(a_row * 128);
    const uint32_t a_xor = (uint32_t)((a_row & 7) << 4);
    const int b_nr   = w_nh * 16 + (lid & 7) + ((grp >> 1) << 3);
    const int b_koff = (grp & 1) << 4;
    const uint32_t b_xor = (uint32_t)((b_nr & 7) << 4);
    const int er = lid >> 2, ec = (lid & 3) * 2;
    const int q = w_mt * 2 + w_nh;

    float2 hreg[2][2], xv[2][2];
#pragma unroll
    for (int rt = 0; rt < 2; ++rt)
#pragma unroll
        for (int j = 0; j < 2; ++j) hreg[rt][j] = make_float2(0.f, 0.f);
    if (kg == 0) {
#pragma unroll
        for (int rt = 0; rt < 2; ++rt) {
            int row = m0 + w_mt * 16 + er + rt * 8;
#pragma unroll
            for (int j = 0; j < 2; ++j)
                xv[rt][j] = *(const float2*)(g_xin + (size_t)row * HIDDEN + j0
                                             + w_nh * 16 + j * 8 + ec);
        }
    }

    for (int t = 0; t < SEQ; ++t) {
        const int cur = t % 3, nx = (t + 1) % 3;
        const __nv_bfloat16* hhi = g_hhi[cur];
        const __nv_bfloat16* hlo = g_hlo[cur];
        const unsigned need = B0 + (unsigned)t;

        float a0[2][4], a1[2][4], a2[2][4];
#pragma unroll
        for (int j = 0; j < 2; ++j)
#pragma unroll
            for (int r = 0; r < 4; ++r) { a0[j][r] = 0.f; a1[j][r] = 0.f; a2[j][r] = 0.f; }

        // poll producers for stage 0 and 1
        if (tid < 16) {
            int ii = tid >> 3, u = tid & 7;
            int pjt = 8 * (u >> 1) + 2 * ii + (u & 1);
            volatile unsigned* f = &g_flags[(mt_blk * 32 + pjt) * 32];
            while ((int)(*f - need) < 0) { }
        }
        __syncthreads();
        stage_quad(sb, hhi, hlo, 0, m0, tid); CP_COMMIT();
        stage_quad(sb, hhi, hlo, 1, m0, tid); CP_COMMIT();

        for (int i = 0; i < 4; ++i) {
            CP_WAIT1();
            __syncthreads();
            if (i + 2 < 4) {
                poll_stage(mt_blk, i + 2, need, tid);
                __syncthreads();
                stage_quad(sb, hhi, hlo, i + 2, m0, tid);
            }
            CP_COMMIT();

            const uint32_t abase = sb + OFF_STAGE + (uint32_t)(i % 3) * 32768u
                                 + (uint32_t)(kg * 8192);
            const uint32_t wbase = sb + OFF_WHI + (uint32_t)((kg * 4 + i) * 4096);
#pragma unroll
            for (int k2 = 0; k2 < 4; ++k2) {
                const uint32_t kb = (uint32_t)(k2 * 32);
                uint32_t ahi[4], alo[4];
                uint32_t aa = abase + a_off + ((kb + a_koff) ^ a_xor);
                ldsm4(ahi[0], ahi[1], ahi[2], ahi[3], aa);
                ldsm4(alo[0], alo[1], alo[2], alo[3], aa + 4096);
                uint32_t bhi[4], blo[4];
                uint32_t ba = wbase + (uint32_t)(b_nr * 128) + ((kb + b_koff) ^ b_xor);
                ldsm4(bhi[0], bhi[1], bhi[2], bhi[3], ba);
                ldsm4(blo[0], blo[1], blo[2], blo[3], ba + (OFF_WLO - OFF_WHI));
#pragma unroll
                for (int j = 0; j < 2; ++j) {
                    mma16816(a0[j], ahi, bhi[j * 2], bhi[j * 2 + 1]);
                    mma16816(a1[j], alo, bhi[j * 2], bhi[j * 2 + 1]);
                    mma16816(a2[j], ahi, blo[j * 2], blo[j * 2 + 1]);
                }
            }
        }
        CP_WAIT0();
        __syncthreads();

        // lagging clobber check (plane nx holds h_{t-2}) + partial publish
        if (kg == 0 && wid == 0) {
            volatile unsigned* f = &g_flags[(mt_blk * 32 + lid) * 32];
            while ((int)(*f - (need - 1)) < 0) { }
        }
        if (kg != 0) {
#pragma unroll
            for (int rt = 0; rt < 2; ++rt)
#pragma unroll
                for (int j = 0; j < 2; ++j)
                    *(float2*)&red[((kg - 1) * 4 + q) * 256 + (rt * 8 + er) * 16 + j * 8 + ec]
                        = make_float2(a0[j][rt * 2] + a1[j][rt * 2] + a2[j][rt * 2],
                                      a0[j][rt * 2 + 1] + a1[j][rt * 2 + 1] + a2[j][rt * 2 + 1]);
        }
        __syncthreads();

        if (kg == 0) {
            uint32_t* hhn = (uint32_t*)g_hhi[nx];
            uint32_t* hln = (uint32_t*)g_hlo[nx];
#pragma unroll
            for (int rt = 0; rt < 2; ++rt) {
                int row = m0 + w_mt * 16 + er + rt * 8;
                size_t rb = (size_t)row * HIDDEN + j0;
#pragma unroll
                for (int j = 0; j < 2; ++j) {
                    int nl = w_nh * 16 + j * 8 + ec;
                    float z0 = a0[j][rt*2] + a1[j][rt*2] + a2[j][rt*2] + xv[rt][j].x + bh_s[nl];
                    float z1 = a0[j][rt*2+1] + a1[j][rt*2+1] + a2[j][rt*2+1]
                             + xv[rt][j].y + bh_s[nl + 1];
#pragma unroll
                    for (int p = 0; p < 3; ++p) {
                        float2 pp = *(float2*)&red[(p * 4 + q) * 256
                                                   + (rt * 8 + er) * 16 + j * 8 + ec];
                        z0 += pp.x; z1 += pp.y;
                    }
                    float d0 = tanhf(z0), d1 = tanhf(z1);
                    float h0 = hreg[rt][j].x + (d0 - hreg[rt][j].x) * itau_s[nl];
                    float h1 = hreg[rt][j].y + (d1 - hreg[rt][j].y) * itau_s[nl + 1];
                    hreg[rt][j] = make_float2(h0, h1);
                    __nv_bfloat16 b0 = __float2bfloat16(h0);
                    __nv_bfloat16 b1 = __float2bfloat16(h1);
                    hhn[(rb + nl) >> 1] = pbf2(h0, h1);
                    hln[(rb + nl) >> 1] = pbf2(h0 - __bfloat162float(b0),
                                               h1 - __bfloat162float(b1));
                    if (t == SEQ - 1)
                        *(float2*)(g_hf + rb + nl) = make_float2(h0, h1);
                }
            }
        }

        __threadfence();
        __syncthreads();
        if (tid == 0) atomicExch(&g_flags[me], need + 1);

        // prefetch next xin (no barrier wait!)
        if (kg == 0) {
            int tp = (t + 1 < SEQ) ? t + 1 : t;
#pragma unroll
            for (int rt = 0; rt < 2; ++rt) {
                int row = m0 + w_mt * 16 + er + rt * 8;
#pragma unroll
                for (int j = 0; j < 2; ++j)
                    xv[rt][j] = *(const float2*)(g_xin + ((size_t)tp * BATCH + row) * HIDDEN
                                                 + j0 + w_nh * 16 + j * 8 + ec);
            }
        }
    }

    grid_sync(gen0 + 2);   // final h visible for phase 3

    if (blockIdx.x < 32) {
        const int b03 = (blockIdx.x >> 3) * 32;
        const int o0  = (blockIdx.x & 7) * 32;
        float* h_s  = (float*)smem;
        float* wo_s = (float*)(smem + OFF_STAGE);
        for (int qq = tid; qq < 32 * 256; qq += 512) {
            int r = qq >> 8, cq = qq & 255;
            float4 v = __ldcg((const float4*)(g_hf + (size_t)(b03 + r) * HIDDEN) + cq);
            *(float4*)&h_s[r * HIDDEN + cq * 4] = v;
        }
        const int ty = tid >> 4, tx = tid & 15;
        float2 acc = *(const float2*)(bout + o0 + tx * 2);
        for (int kc = 0; kc < 16; ++kc) {
            __syncthreads();
            {
                int r = tid >> 3, c4 = tid & 7;
                *(float4*)&wo_s[r * 32 + c4 * 4] =
                    *(const float4*)(Wout + (size_t)(kc * 64 + r) * OUTPUT + o0 + c4 * 4);
            }
            __syncthreads();
#pragma unroll 16
            for (int kk = 0; kk < 64; ++kk) {
                float hvv = h_s[ty * HIDDEN + kc * 64 + kk];
                float2 w = *(const float2*)&wo_s[kk * 32 + tx * 2];
                acc.x += hvv * w.x; acc.y += hvv * w.y;
            }
        }
        *(float2*)(out + (size_t)(b03 + ty) * OUTPUT + o0 + tx * 2) = acc;
    }
}

extern "C" void kernel_launch(void* const* d_in, const int* in_sizes, int n_in,
                              void* d_out, int out_size)
{
    const float* x    = (const float*)d_in[0];
    const float* Win  = (const float*)d_in[1];
    const float* bin  = (const float*)d_in[2];
    const float* Wh   = (const float*)d_in[3];
    const float* bhp  = (const float*)d_in[4];
    const float* tau  = (const float*)d_in[5];
    const float* Wout = (const float*)d_in[6];
    const float* bout = (const float*)d_in[7];
    float* out = (float*)d_out;

    cudaFuncSetAttribute(gemm_xin_mma, cudaFuncAttributeMaxDynamicSharedMemorySize, GEMM_SMEM);
    cudaFuncSetAttribute(scan_mma_kernel, cudaFuncAttributeMaxDynamicSharedMemorySize, SCAN_SMEM);

    conv_x_kernel<<<4096, 256>>>(x);
    conv_w_kernel<<<(INPUT * HIDDEN + 255) / 256, 256>>>(Win);

    dim3 gg(HIDDEN / 64, (BATCH * SEQ) / 128);
    gemm_xin_mma<<<gg, 256, GEMM_SMEM>>>(bin);

    scan_mma_kernel<<<NBLK, 512, SCAN_SMEM>>>(Wh, bhp, tau, Wout, bout, out);
}

// round 10
// speedup vs baseline: 1.0179x; 1.0179x over previous
#include <cuda_runtime.h>
#include <cuda_bf16.h>
#include <math.h>
#include <stdint.h>

#define BATCH   128
#define SEQ     512
#define INPUT   512
#define HIDDEN  1024
#define OUTPUT  256
#define NBLK    128
#define JW      32
#define MW      32

__device__ float          g_xin[(size_t)SEQ * BATCH * HIDDEN];
__device__ float          g_hf[BATCH * HIDDEN];
__device__ __nv_bfloat16  g_hhi[3][BATCH * HIDDEN];
__device__ __nv_bfloat16  g_hlo[3][BATCH * HIDDEN];
__device__ __nv_bfloat16  g_xhi[(size_t)BATCH * SEQ * INPUT];
__device__ __nv_bfloat16  g_xlo[(size_t)BATCH * SEQ * INPUT];
__device__ __nv_bfloat16  g_wThi[HIDDEN * INPUT];
__device__ __nv_bfloat16  g_wTlo[HIDDEN * INPUT];
__device__ unsigned g_flags[NBLK * 32];
__device__ unsigned g_bar_cnt;
__device__ unsigned g_bar_gen;

#define OFF_WHI    0
#define OFF_WLO    65536
#define OFF_STAGE  131072
#define OFF_RED    OFF_STAGE
#define OFF_BH     229376
#define OFF_ITAU   229504
#define OFF_GEN0   229632
#define SCAN_SMEM  229696

#define OFF_GA     0
#define OFF_GB     98304
#define OFF_BIN    147456
#define GEMM_SMEM  147968

__device__ __forceinline__ uint32_t smem_u32(const void* p) {
    uint32_t a;
    asm("{ .reg .u64 t; cvta.to.shared.u64 t, %1; cvt.u32.u64 %0, t; }" : "=r"(a) : "l"(p));
    return a;
}
#define CP_COMMIT() asm volatile("cp.async.commit_group;" ::: "memory")
#define CP_WAIT1()  asm volatile("cp.async.wait_group 1;" ::: "memory")
#define CP_WAIT0()  asm volatile("cp.async.wait_group 0;" ::: "memory")

__device__ __forceinline__ void cp16(uint32_t dst, const void* src) {
    asm volatile("cp.async.cg.shared.global [%0], [%1], 16;" :: "r"(dst), "l"(src) : "memory");
}
__device__ __forceinline__ void ldsm4(uint32_t& r0, uint32_t& r1, uint32_t& r2, uint32_t& r3,
                                      uint32_t a) {
    asm volatile("ldmatrix.sync.aligned.m8n8.x4.shared.b16 {%0,%1,%2,%3}, [%4];"
                 : "=r"(r0), "=r"(r1), "=r"(r2), "=r"(r3) : "r"(a));
}
__device__ __forceinline__ void mma16816(float* d, const uint32_t* a, uint32_t b0, uint32_t b1) {
    asm volatile("mma.sync.aligned.m16n8k16.row.col.f32.bf16.bf16.f32 "
                 "{%0,%1,%2,%3}, {%4,%5,%6,%7}, {%8,%9}, {%0,%1,%2,%3};"
                 : "+f"(d[0]), "+f"(d[1]), "+f"(d[2]), "+f"(d[3])
                 : "r"(a[0]), "r"(a[1]), "r"(a[2]), "r"(a[3]), "r"(b0), "r"(b1));
}
__device__ __forceinline__ uint32_t pbf2(float a, float b) {
    __nv_bfloat162 t = __floats2bfloat162_rn(a, b);
    return *(uint32_t*)&t;
}
__device__ __forceinline__ void rel_store(unsigned* p, unsigned v) {
    asm volatile("st.release.gpu.global.u32 [%0], %1;" :: "l"(p), "r"(v) : "memory");
}
__device__ __forceinline__ unsigned acq_load(unsigned* p) {
    unsigned v;
    asm volatile("ld.acquire.gpu.global.u32 %0, [%1];" : "=r"(v) : "l"(p) : "memory");
    return v;
}
__device__ __forceinline__ void grid_sync(unsigned target)
{
    __threadfence();
    __syncthreads();
    if (threadIdx.x == 0) {
        unsigned arrived = atomicAdd(&g_bar_cnt, 1u);
        if (arrived == NBLK - 1) {
            atomicExch(&g_bar_cnt, 0u);
            __threadfence();
            atomicAdd(&g_bar_gen, 1u);
        } else {
            while ((int)(*(volatile unsigned*)&g_bar_gen - target) < 0) { }
            __threadfence();
        }
    }
    __syncthreads();
}

__global__ __launch_bounds__(256) void conv_x_kernel(const float* __restrict__ x)
{
    const size_t total = (size_t)BATCH * SEQ * INPUT / 2;
    size_t base = (size_t)blockIdx.x * 256 + threadIdx.x;
    size_t stride = (size_t)gridDim.x * 256;
    uint32_t* xhi = (uint32_t*)g_xhi;
    uint32_t* xlo = (uint32_t*)g_xlo;
    for (size_t p = base; p < total; p += stride) {
        float2 v = ((const float2*)x)[p];
        uint32_t hp = pbf2(v.x, v.y);
        __nv_bfloat162 hb = *(__nv_bfloat162*)&hp;
        xhi[p] = hp;
        xlo[p] = pbf2(v.x - __bfloat162float(hb.x), v.y - __bfloat162float(hb.y));
    }
}

__global__ __launch_bounds__(256) void conv_w_kernel(const float* __restrict__ Win)
{
    int idx = blockIdx.x * 256 + threadIdx.x;
    if (idx >= INPUT * HIDDEN) return;
    int k = idx >> 10, n = idx & 1023;
    float w = Win[idx];
    __nv_bfloat16 whi = __float2bfloat16(w);
    g_wThi[(size_t)n * INPUT + k] = whi;
    g_wTlo[(size_t)n * INPUT + k] = __float2bfloat16(w - __bfloat162float(whi));
}

// ---------------- Phase 1 GEMM (unchanged, proven) ----------------
__device__ __forceinline__ void gstage(uint32_t sb, int kc, int m0, int n0, int tid)
{
    uint32_t abase = sb + OFF_GA + (uint32_t)(kc % 3) * 32768u;
    uint32_t bbase = sb + OFF_GB + (uint32_t)(kc % 3) * 16384u;
#pragma unroll
    for (int u = 0; u < 8; ++u) {
        int g = tid + u * 256;
        int seg = g & 7, row = (g >> 3) & 127, plane = g >> 10;
        const char* src = (const char*)(plane ? g_xlo : g_xhi)
                        + (size_t)(m0 + row) * 1024 + (size_t)kc * 128 + seg * 16;
        cp16(abase + plane * 16384 + row * 128 + ((seg * 16) ^ ((row & 7) << 4)), src);
    }
#pragma unroll
    for (int u = 0; u < 4; ++u) {
        int g = tid + u * 256;
        int seg = g & 7, row = (g >> 3) & 63, plane = g >> 9;
        const char* src = (const char*)(plane ? g_wTlo : g_wThi)
                        + (size_t)(n0 + row) * 1024 + (size_t)kc * 128 + seg * 16;
        cp16(bbase + plane * 8192 + row * 128 + ((seg * 16) ^ ((row & 7) << 4)), src);
    }
}

__global__ __launch_bounds__(256, 1) void gemm_xin_mma(const float* __restrict__ bin)
{
    extern __shared__ __align__(1024) char smem[];
    const uint32_t sb = smem_u32(smem);
    const int tid = threadIdx.x, wid = tid >> 5, lid = tid & 31;
    const int n0 = blockIdx.x * 64, m0 = blockIdx.y * 128;
    const int mq = wid & 3, nh = wid >> 2;
    float* bin_s = (float*)(smem + OFF_BIN);
    if (tid < 16) ((float4*)bin_s)[tid] = ((const float4*)(bin + n0))[tid];

    const int grp = lid >> 3;
    int a_rowl[2];
    a_rowl[0] = mq * 32 + (lid & 7) + ((grp & 1) << 3);
    a_rowl[1] = a_rowl[0] + 16;
    const int a_koff = (grp >> 1) << 4;
    const int b_nr   = nh * 32 + (lid & 7) + ((grp >> 1) << 3);
    const int b_koff = (grp & 1) << 4;
    const uint32_t b_xor = (uint32_t)((b_nr & 7) << 4);

    float acc[2][4][4];
#pragma unroll
    for (int i = 0; i < 2; ++i)
#pragma unroll
        for (int j = 0; j < 4; ++j)
#pragma unroll
            for (int r = 0; r < 4; ++r) acc[i][j][r] = 0.0f;

    gstage(sb, 0, m0, n0, tid); CP_COMMIT();
    gstage(sb, 1, m0, n0, tid); CP_COMMIT();

    for (int kc = 0; kc < 8; ++kc) {
        CP_WAIT1();
        __syncthreads();
        if (kc + 2 < 8) gstage(sb, kc + 2, m0, n0, tid);
        CP_COMMIT();
        const uint32_t abase = sb + OFF_GA + (uint32_t)(kc % 3) * 32768u;
        const uint32_t bbase = sb + OFF_GB + (uint32_t)(kc % 3) * 16384u;
#pragma unroll
        for (int k2 = 0; k2 < 4; ++k2) {
            const uint32_t kb = (uint32_t)(k2 * 32);
            uint32_t ahi[2][4], alo[2][4];
#pragma unroll
            for (int mt = 0; mt < 2; ++mt) {
                uint32_t aa = abase + (uint32_t)(a_rowl[mt] * 128)
                            + ((kb + a_koff) ^ ((a_rowl[mt] & 7) << 4));
                ldsm4(ahi[mt][0], ahi[mt][1], ahi[mt][2], ahi[mt][3], aa);
                ldsm4(alo[mt][0], alo[mt][1], alo[mt][2], alo[mt][3], aa + 16384);
            }
            uint32_t bhi[8], blo[8];
            {
                uint32_t ba = bbase + (uint32_t)(b_nr * 128) + ((kb + b_koff) ^ b_xor);
                ldsm4(bhi[0], bhi[1], bhi[2], bhi[3], ba);
                ldsm4(bhi[4], bhi[5], bhi[6], bhi[7], ba + 2048);
                ldsm4(blo[0], blo[1], blo[2], blo[3], ba + 8192);
                ldsm4(blo[4], blo[5], blo[6], blo[7], ba + 8192 + 2048);
            }
#pragma unroll
            for (int mt = 0; mt < 2; ++mt)
#pragma unroll
                for (int j = 0; j < 4; ++j) {
                    mma16816(acc[mt][j], ahi[mt], bhi[j * 2], bhi[j * 2 + 1]);
                    mma16816(acc[mt][j], alo[mt], bhi[j * 2], bhi[j * 2 + 1]);
                    mma16816(acc[mt][j], ahi[mt], blo[j * 2], blo[j * 2 + 1]);
                }
        }
    }

    const int er = lid >> 2, ec = (lid & 3) * 2;
#pragma unroll
    for (int mt = 0; mt < 2; ++mt)
#pragma unroll
        for (int rt = 0; rt < 2; ++rt) {
            int m = m0 + mq * 32 + mt * 16 + er + rt * 8;
            int b = m >> 9, s = m & 511;
            float* orow = g_xin + ((size_t)s * BATCH + b) * HIDDEN + n0;
#pragma unroll
            for (int j = 0; j < 4; ++j) {
                int nl = nh * 32 + j * 8 + ec;
                float2 v;
                v.x = acc[mt][j][rt * 2 + 0] + bin_s[nl];
                v.y = acc[mt][j][rt * 2 + 1] + bin_s[nl + 1];
                *(float2*)(orow + nl) = v;
            }
        }
}

// ---------------- Scan ----------------
__device__ __forceinline__ void stage_quad(uint32_t sb, const __nv_bfloat16* hi,
                                           const __nv_bfloat16* lo, int i, int m0, int tid)
{
    uint32_t base = sb + OFF_STAGE + (uint32_t)(i % 3) * 32768u;
#pragma unroll
    for (int u = 0; u < 4; ++u) {
        int g = tid + u * 512;
        int seg = g & 7, row = (g >> 3) & 31, plane = (g >> 8) & 1, kg = g >> 9;
        int c = kg * 4 + i;
        const char* src = (const char*)(plane ? lo : hi)
                        + (size_t)(m0 + row) * 2048 + (size_t)c * 128 + seg * 16;
        cp16(base + kg * 8192 + plane * 4096 + row * 128 + ((seg * 16) ^ ((row & 7) << 4)), src);
    }
}

__device__ __forceinline__ void poll_stage(int mt, int i, unsigned need, int tid)
{
    if (tid < 8) {
        int jt = 8 * (tid >> 1) + 2 * i + (tid & 1);
        unsigned* f = &g_flags[(mt * 32 + jt) * 32];
        while ((int)(acq_load(f) - need) < 0) { }
    }
}

__global__ __launch_bounds__(512, 1) void scan_mma_kernel(
    const float* __restrict__ Wh,  const float* __restrict__ bh,
    const float* __restrict__ tau, const float* __restrict__ Wout,
    const float* __restrict__ bout, float* __restrict__ out)
{
    extern __shared__ __align__(1024) char smem[];
    const uint32_t sb = smem_u32(smem);
    const int tid = threadIdx.x, wid = tid >> 5, lid = tid & 31;
    const int jt = blockIdx.x >> 2, mt_blk = blockIdx.x & 3;
    const int j0 = jt * JW, m0 = mt_blk * MW;
    const int me = (mt_blk * 32 + jt) * 32;
    float* bh_s   = (float*)(smem + OFF_BH);
    float* itau_s = (float*)(smem + OFF_ITAU);
    float* red    = (float*)(smem + OFF_RED);

    if (tid == 0) {
        ((unsigned*)(smem + OFF_GEN0))[0] = *(volatile unsigned*)&g_bar_gen;
        ((unsigned*)(smem + OFF_GEN0))[1] = *(volatile unsigned*)&g_flags[me];
    }
    if (tid < JW) {
        bh_s[tid]   = bh[j0 + tid];
        itau_s[tid] = 1.0f / tau[j0 + tid];
    }

    for (int idx = tid; idx < 1024 * 8; idx += 512) {
        int k = idx >> 3, nq = idx & 7;
        float4 wv = *(const float4*)(Wh + (size_t)k * HIDDEN + j0 + nq * 4);
        float w[4] = {wv.x, wv.y, wv.z, wv.w};
#pragma unroll
        for (int e = 0; e < 4; ++e) {
            int n = nq * 4 + e;
            uint32_t so = (uint32_t)((k >> 6) * 4096 + n * 128)
                        + (uint32_t)((((k & 63) * 2) ^ ((n & 7) << 4)));
            __nv_bfloat16 whi = __float2bfloat16(w[e]);
            *(__nv_bfloat16*)(smem + OFF_WHI + so) = whi;
            *(__nv_bfloat16*)(smem + OFF_WLO + so) =
                __float2bfloat16(w[e] - __bfloat162float(whi));
        }
    }
    for (int idx = tid; idx < MW * JW / 2; idx += 512) {
        int r = idx / (JW / 2), c = idx % (JW / 2);
        size_t o = (size_t)(m0 + r) * HIDDEN + j0 + c * 2;
        *(uint32_t*)(g_hhi[0] + o) = 0u;
        *(uint32_t*)(g_hlo[0] + o) = 0u;
    }
    __syncthreads();
    const unsigned gen0 = ((unsigned*)(smem + OFF_GEN0))[0];
    const unsigned B0   = ((unsigned*)(smem + OFF_GEN0))[1];

    grid_sync(gen0 + 1);

    const int w_mt = wid & 1, w_nh = (wid >> 1) & 1, kg = wid >> 2;
    const int grp = lid >> 3;
    const int a_row  = w_mt * 16 + (lid & 7) + ((grp & 1) << 3);
    const int a_koff = (grp >> 1) << 4;
    const uint32_t a_off = (uint32_t)(a_row * 128);
    const uint32_t a_xor = (uint32_t)((a_row & 7) << 4);
    const int b_nr   = w_nh * 16 + (lid & 7) + ((grp >> 1) << 3);
    const int b_koff = (grp & 1) << 4;
    const uint32_t b_xor = (uint32_t)((b_nr & 7) << 4);
    const int er = lid >> 2, ec = (lid & 3) * 2;
    const int q = w_mt * 2 + w_nh;

    // per-thread output ownership: row = tid>>4, cols 2*(tid&15), +1
    const int orow = tid >> 4, ocp = (tid & 15) * 2;
    const int rw_mt = orow >> 4, rlr = orow & 15, rw_nh = ocp >> 4, rlc = ocp & 15;
    const float obh0 = bh_s[ocp], obh1 = bh_s[ocp + 1];
    const float oit0 = itau_s[ocp], oit1 = itau_s[ocp + 1];
    float2 hreg = make_float2(0.f, 0.f);
    float2 xv = *(const float2*)(g_xin + (size_t)(m0 + orow) * HIDDEN + j0 + ocp);

    for (int t = 0; t < SEQ; ++t) {
        const int cur = t % 3, nx = (t + 1) % 3;
        const __nv_bfloat16* hhi = g_hhi[cur];
        const __nv_bfloat16* hlo = g_hlo[cur];
        const unsigned need = B0 + (unsigned)t;

        float a0[2][4], a1[2][4], a2[2][4];
#pragma unroll
        for (int j = 0; j < 2; ++j)
#pragma unroll
            for (int r = 0; r < 4; ++r) { a0[j][r] = 0.f; a1[j][r] = 0.f; a2[j][r] = 0.f; }

        if (tid < 16) {
            int ii = tid >> 3, u = tid & 7;
            int pjt = 8 * (u >> 1) + 2 * ii + (u & 1);
            unsigned* f = &g_flags[(mt_blk * 32 + pjt) * 32];
            while ((int)(acq_load(f) - need) < 0) { }
        }
        __syncthreads();
        stage_quad(sb, hhi, hlo, 0, m0, tid); CP_COMMIT();
        stage_quad(sb, hhi, hlo, 1, m0, tid); CP_COMMIT();

        for (int i = 0; i < 4; ++i) {
            CP_WAIT1();
            __syncthreads();
            if (i + 2 < 4) {
                poll_stage(mt_blk, i + 2, need, tid);
                __syncthreads();
                stage_quad(sb, hhi, hlo, i + 2, m0, tid);
            }
            CP_COMMIT();

            const uint32_t abase = sb + OFF_STAGE + (uint32_t)(i % 3) * 32768u
                                 + (uint32_t)(kg * 8192);
            const uint32_t wbase = sb + OFF_WHI + (uint32_t)((kg * 4 + i) * 4096);
#pragma unroll
            for (int k2 = 0; k2 < 4; ++k2) {
                const uint32_t kb = (uint32_t)(k2 * 32);
                uint32_t ahi[4], alo[4];
                uint32_t aa = abase + a_off + ((kb + a_koff) ^ a_xor);
                ldsm4(ahi[0], ahi[1], ahi[2], ahi[3], aa);
                ldsm4(alo[0], alo[1], alo[2], alo[3], aa + 4096);
                uint32_t bhi[4], blo[4];
                uint32_t ba = wbase + (uint32_t)(b_nr * 128) + ((kb + b_koff) ^ b_xor);
                ldsm4(bhi[0], bhi[1], bhi[2], bhi[3], ba);
                ldsm4(blo[0], blo[1], blo[2], blo[3], ba + (OFF_WLO - OFF_WHI));
#pragma unroll
                for (int j = 0; j < 2; ++j) {
                    mma16816(a0[j], ahi, bhi[j * 2], bhi[j * 2 + 1]);
                    mma16816(a1[j], alo, bhi[j * 2], bhi[j * 2 + 1]);
                    mma16816(a2[j], ahi, blo[j * 2], blo[j * 2 + 1]);
                }
            }
        }
        CP_WAIT0();
        __syncthreads();

        // clobber guard: all group blocks past step t-2 (plane nx free)
        if (wid == 0) {
            unsigned* f = &g_flags[(mt_blk * 32 + lid) * 32];
            while ((int)(acq_load(f) - (need - 1)) < 0) { }
        }
        // ALL warps publish 3-term-summed partials
#pragma unroll
        for (int rt = 0; rt < 2; ++rt)
#pragma unroll
            for (int j = 0; j < 2; ++j)
                *(float2*)&red[(kg * 4 + q) * 256 + (rt * 8 + er) * 16 + j * 8 + ec]
                    = make_float2(a0[j][rt * 2] + a1[j][rt * 2] + a2[j][rt * 2],
                                  a0[j][rt * 2 + 1] + a1[j][rt * 2 + 1] + a2[j][rt * 2 + 1]);
        __syncthreads();

        // per-thread epilogue: 2 outputs each (all 512 threads)
        {
            float z0 = xv.x + obh0, z1 = xv.y + obh1;
#pragma unroll
            for (int kg2 = 0; kg2 < 4; ++kg2) {
                float2 pp = *(float2*)&red[(kg2 * 4 + rw_mt * 2 + rw_nh) * 256
                                           + rlr * 16 + rlc];
                z0 += pp.x; z1 += pp.y;
            }
            float d0 = tanhf(z0), d1 = tanhf(z1);
            float h0 = hreg.x + (d0 - hreg.x) * oit0;
            float h1 = hreg.y + (d1 - hreg.y) * oit1;
            hreg = make_float2(h0, h1);
            size_t rb = (size_t)(m0 + orow) * HIDDEN + j0 + ocp;
            __nv_bfloat16 b0 = __float2bfloat16(h0);
            __nv_bfloat16 b1 = __float2bfloat16(h1);
            ((uint32_t*)g_hhi[nx])[rb >> 1] = pbf2(h0, h1);
            ((uint32_t*)g_hlo[nx])[rb >> 1] = pbf2(h0 - __bfloat162float(b0),
                                                   h1 - __bfloat162float(b1));
            if (t == SEQ - 1) *(float2*)(g_hf + rb) = make_float2(h0, h1);
        }

        __syncthreads();                       // all stores issued (cumulativity anchor)
        if (tid == 0) rel_store(&g_flags[me], need + 1);

        // prefetch next xin off the critical path
        {
            int tp = (t + 1 < SEQ) ? t + 1 : t;
            xv = *(const float2*)(g_xin + ((size_t)tp * BATCH + m0 + orow) * HIDDEN + j0 + ocp);
        }
    }

    grid_sync(gen0 + 2);

    if (blockIdx.x < 32) {
        const int b03 = (blockIdx.x >> 3) * 32;
        const int o0  = (blockIdx.x & 7) * 32;
        float* h_s  = (float*)smem;
        float* wo_s = (float*)(smem + OFF_STAGE);
        for (int qq = tid; qq < 32 * 256; qq += 512) {
            int r = qq >> 8, cq = qq & 255;
            float4 v = __ldcg((const float4*)(g_hf + (size_t)(b03 + r) * HIDDEN) + cq);
            *(float4*)&h_s[r * HIDDEN + cq * 4] = v;
        }
        const int ty = tid >> 4, tx = tid & 15;
        float2 acc = *(const float2*)(bout + o0 + tx * 2);
        for (int kc = 0; kc < 16; ++kc) {
            __syncthreads();
            {
                int r = tid >> 3, c4 = tid & 7;
                *(float4*)&wo_s[r * 32 + c4 * 4] =
                    *(const float4*)(Wout + (size_t)(kc * 64 + r) * OUTPUT + o0 + c4 * 4);
            }
            __syncthreads();
#pragma unroll 16
            for (int kk = 0; kk < 64; ++kk) {
                float hvv = h_s[ty * HIDDEN + kc * 64 + kk];
                float2 w = *(const float2*)&wo_s[kk * 32 + tx * 2];
                acc.x += hvv * w.x; acc.y += hvv * w.y;
            }
        }
        *(float2*)(out + (size_t)(b03 + ty) * OUTPUT + o0 + tx * 2) = acc;
    }
}

extern "C" void kernel_launch(void* const* d_in, const int* in_sizes, int n_in,
                              void* d_out, int out_size)
{
    const float* x    = (const float*)d_in[0];
    const float* Win  = (const float*)d_in[1];
    const float* bin  = (const float*)d_in[2];
    const float* Wh   = (const float*)d_in[3];
    const float* bhp  = (const float*)d_in[4];
    const float* tau  = (const float*)d_in[5];
    const float* Wout = (const float*)d_in[6];
    const float* bout = (const float*)d_in[7];
    float* out = (float*)d_out;

    cudaFuncSetAttribute(gemm_xin_mma, cudaFuncAttributeMaxDynamicSharedMemorySize, GEMM_SMEM);
    cudaFuncSetAttribute(scan_mma_kernel, cudaFuncAttributeMaxDynamicSharedMemorySize, SCAN_SMEM);

    conv_x_kernel<<<4096, 256>>>(x);
    conv_w_kernel<<<(INPUT * HIDDEN + 255) / 256, 256>>>(Win);

    dim3 gg(HIDDEN / 64, (BATCH * SEQ) / 128);
    gemm_xin_mma<<<gg, 256, GEMM_SMEM>>>(bin);

    scan_mma_kernel<<<NBLK, 512, SCAN_SMEM>>>(Wh, bhp, tau, Wout, bout, out);
}

// round 11
// speedup vs baseline: 1.0351x; 1.0170x over previous
#include <cuda_runtime.h>
#include <cuda_bf16.h>
#include <math.h>
#include <stdint.h>

#define BATCH   128
#define SEQ     512
#define INPUT   512
#define HIDDEN  1024
#define OUTPUT  256
#define NBLK    128
#define JW      32
#define MW      32

__device__ float          g_xin[(size_t)SEQ * BATCH * HIDDEN];
__device__ float          g_hf[BATCH * HIDDEN];
__device__ __nv_bfloat16  g_hhi[3][BATCH * HIDDEN];
__device__ __nv_bfloat16  g_hlo[3][BATCH * HIDDEN];
__device__ __nv_bfloat16  g_xhi[(size_t)BATCH * SEQ * INPUT];
__device__ __nv_bfloat16  g_xlo[(size_t)BATCH * SEQ * INPUT];
__device__ __nv_bfloat16  g_wThi[HIDDEN * INPUT];
__device__ __nv_bfloat16  g_wTlo[HIDDEN * INPUT];
__device__ unsigned g_flags[NBLK * 32];
__device__ unsigned g_bar_cnt;
__device__ unsigned g_bar_gen;

#define OFF_WHI    0
#define OFF_WLO    65536
#define OFF_STAGE  131072
#define OFF_RED    OFF_STAGE
#define OFF_BH     229376
#define OFF_ITAU   229504
#define OFF_GEN0   229632
#define SCAN_SMEM  229696

// gemm: A 3 x 32KB, B 3 x 32KB, bin 512B
#define OFF_GA     0
#define OFF_GB     98304
#define OFF_BIN    196608
#define GEMM_SMEM  197120

__device__ __forceinline__ uint32_t smem_u32(const void* p) {
    uint32_t a;
    asm("{ .reg .u64 t; cvta.to.shared.u64 t, %1; cvt.u32.u64 %0, t; }" : "=r"(a) : "l"(p));
    return a;
}
#define CP_COMMIT() asm volatile("cp.async.commit_group;" ::: "memory")
#define CP_WAIT1()  asm volatile("cp.async.wait_group 1;" ::: "memory")
#define CP_WAIT0()  asm volatile("cp.async.wait_group 0;" ::: "memory")

__device__ __forceinline__ void cp16(uint32_t dst, const void* src) {
    asm volatile("cp.async.cg.shared.global [%0], [%1], 16;" :: "r"(dst), "l"(src) : "memory");
}
__device__ __forceinline__ void ldsm4(uint32_t& r0, uint32_t& r1, uint32_t& r2, uint32_t& r3,
                                      uint32_t a) {
    asm volatile("ldmatrix.sync.aligned.m8n8.x4.shared.b16 {%0,%1,%2,%3}, [%4];"
                 : "=r"(r0), "=r"(r1), "=r"(r2), "=r"(r3) : "r"(a));
}
__device__ __forceinline__ void mma16816(float* d, const uint32_t* a, uint32_t b0, uint32_t b1) {
    asm volatile("mma.sync.aligned.m16n8k16.row.col.f32.bf16.bf16.f32 "
                 "{%0,%1,%2,%3}, {%4,%5,%6,%7}, {%8,%9}, {%0,%1,%2,%3};"
                 : "+f"(d[0]), "+f"(d[1]), "+f"(d[2]), "+f"(d[3])
                 : "r"(a[0]), "r"(a[1]), "r"(a[2]), "r"(a[3]), "r"(b0), "r"(b1));
}
__device__ __forceinline__ uint32_t pbf2(float a, float b) {
    __nv_bfloat162 t = __floats2bfloat162_rn(a, b);
    return *(uint32_t*)&t;
}
__device__ __forceinline__ void rel_store(unsigned* p, unsigned v) {
    asm volatile("st.release.gpu.global.u32 [%0], %1;" :: "l"(p), "r"(v) : "memory");
}
__device__ __forceinline__ unsigned acq_load(unsigned* p) {
    unsigned v;
    asm volatile("ld.acquire.gpu.global.u32 %0, [%1];" : "=r"(v) : "l"(p) : "memory");
    return v;
}
__device__ __forceinline__ void grid_sync(unsigned target)
{
    __threadfence();
    __syncthreads();
    if (threadIdx.x == 0) {
        unsigned arrived = atomicAdd(&g_bar_cnt, 1u);
        if (arrived == NBLK - 1) {
            atomicExch(&g_bar_cnt, 0u);
            __threadfence();
            atomicAdd(&g_bar_gen, 1u);
        } else {
            while ((int)(*(volatile unsigned*)&g_bar_gen - target) < 0) { }
            __threadfence();
        }
    }
    __syncthreads();
}

__global__ __launch_bounds__(256) void conv_x_kernel(const float* __restrict__ x)
{
    const size_t total = (size_t)BATCH * SEQ * INPUT / 2;
    size_t base = (size_t)blockIdx.x * 256 + threadIdx.x;
    size_t stride = (size_t)gridDim.x * 256;
    uint32_t* xhi = (uint32_t*)g_xhi;
    uint32_t* xlo = (uint32_t*)g_xlo;
    for (size_t p = base; p < total; p += stride) {
        float2 v = ((const float2*)x)[p];
        uint32_t hp = pbf2(v.x, v.y);
        __nv_bfloat162 hb = *(__nv_bfloat162*)&hp;
        xhi[p] = hp;
        xlo[p] = pbf2(v.x - __bfloat162float(hb.x), v.y - __bfloat162float(hb.y));
    }
}

__global__ __launch_bounds__(256) void conv_w_kernel(const float* __restrict__ Win)
{
    int idx = blockIdx.x * 256 + threadIdx.x;
    if (idx >= INPUT * HIDDEN) return;
    int k = idx >> 10, n = idx & 1023;
    float w = Win[idx];
    __nv_bfloat16 whi = __float2bfloat16(w);
    g_wThi[(size_t)n * INPUT + k] = whi;
    g_wTlo[(size_t)n * INPUT + k] = __float2bfloat16(w - __bfloat162float(whi));
}

// ---------------- Phase 1 GEMM: M=128, N=128, BK=64 ----------------
__device__ __forceinline__ void gstage(uint32_t sb, int kc, int m0, int n0, int tid)
{
    uint32_t abase = sb + OFF_GA + (uint32_t)(kc % 3) * 32768u;
    uint32_t bbase = sb + OFF_GB + (uint32_t)(kc % 3) * 32768u;
#pragma unroll
    for (int u = 0; u < 8; ++u) {                    // A: 2048 cp16
        int g = tid + u * 256;
        int seg = g & 7, row = (g >> 3) & 127, plane = g >> 10;
        const char* src = (const char*)(plane ? g_xlo : g_xhi)
                        + (size_t)(m0 + row) * 1024 + (size_t)kc * 128 + seg * 16;
        cp16(abase + plane * 16384 + row * 128 + ((seg * 16) ^ ((row & 7) << 4)), src);
    }
#pragma unroll
    for (int u = 0; u < 8; ++u) {                    // B: 2048 cp16 (128 n-rows)
        int g = tid + u * 256;
        int seg = g & 7, row = (g >> 3) & 127, plane = g >> 10;
        const char* src = (const char*)(plane ? g_wTlo : g_wThi)
                        + (size_t)(n0 + row) * 1024 + (size_t)kc * 128 + seg * 16;
        cp16(bbase + plane * 16384 + row * 128 + ((seg * 16) ^ ((row & 7) << 4)), src);
    }
}

__global__ __launch_bounds__(256, 1) void gemm_xin_mma(const float* __restrict__ bin)
{
    extern __shared__ __align__(1024) char smem[];
    const uint32_t sb = smem_u32(smem);
    const int tid = threadIdx.x, wid = tid >> 5, lid = tid & 31;
    const int n0 = blockIdx.x * 128, m0 = blockIdx.y * 128;
    const int mq = wid & 3, nh = wid >> 2;           // 4 m-warps x 2 n-warps (n64 each)
    float* bin_s = (float*)(smem + OFF_BIN);
    if (tid < 32) ((float4*)bin_s)[tid] = ((const float4*)(bin + n0))[tid];

    const int grp = lid >> 3;
    int a_rowl[2];
    a_rowl[0] = mq * 32 + (lid & 7) + ((grp & 1) << 3);
    a_rowl[1] = a_rowl[0] + 16;
    const int a_koff = (grp >> 1) << 4;
    const int b_nr   = nh * 64 + (lid & 7) + ((grp >> 1) << 3);
    const int b_koff = (grp & 1) << 4;
    const uint32_t b_xor = (uint32_t)((b_nr & 7) << 4);

    float acc[2][8][4];
#pragma unroll
    for (int i = 0; i < 2; ++i)
#pragma unroll
        for (int j = 0; j < 8; ++j)
#pragma unroll
            for (int r = 0; r < 4; ++r) acc[i][j][r] = 0.0f;

    gstage(sb, 0, m0, n0, tid); CP_COMMIT();
    gstage(sb, 1, m0, n0, tid); CP_COMMIT();

    for (int kc = 0; kc < 8; ++kc) {
        CP_WAIT1();
        __syncthreads();
        if (kc + 2 < 8) gstage(sb, kc + 2, m0, n0, tid);
        CP_COMMIT();
        const uint32_t abase = sb + OFF_GA + (uint32_t)(kc % 3) * 32768u;
        const uint32_t bbase = sb + OFF_GB + (uint32_t)(kc % 3) * 32768u;
#pragma unroll
        for (int k2 = 0; k2 < 4; ++k2) {
            const uint32_t kb = (uint32_t)(k2 * 32);
            uint32_t ahi[2][4], alo[2][4];
#pragma unroll
            for (int mt = 0; mt < 2; ++mt) {
                uint32_t aa = abase + (uint32_t)(a_rowl[mt] * 128)
                            + ((kb + a_koff) ^ ((a_rowl[mt] & 7) << 4));
                ldsm4(ahi[mt][0], ahi[mt][1], ahi[mt][2], ahi[mt][3], aa);
                ldsm4(alo[mt][0], alo[mt][1], alo[mt][2], alo[mt][3], aa + 16384);
            }
            uint32_t bhi[16], blo[16];
#pragma unroll
            for (int bt = 0; bt < 4; ++bt) {         // n-frags 2bt, 2bt+1
                uint32_t ba = bbase + (uint32_t)((b_nr + 16 * bt) * 128)
                            + ((kb + b_koff) ^ b_xor);
                ldsm4(bhi[bt * 4 + 0], bhi[bt * 4 + 1], bhi[bt * 4 + 2], bhi[bt * 4 + 3], ba);
                ldsm4(blo[bt * 4 + 0], blo[bt * 4 + 1], blo[bt * 4 + 2], blo[bt * 4 + 3],
                      ba + 16384);
            }
#pragma unroll
            for (int mt = 0; mt < 2; ++mt)
#pragma unroll
                for (int j = 0; j < 8; ++j) {
                    mma16816(acc[mt][j], ahi[mt], bhi[j * 2], bhi[j * 2 + 1]);
                    mma16816(acc[mt][j], alo[mt], bhi[j * 2], bhi[j * 2 + 1]);
                    mma16816(acc[mt][j], ahi[mt], blo[j * 2], blo[j * 2 + 1]);
                }
        }
    }

    const int er = lid >> 2, ec = (lid & 3) * 2;
#pragma unroll
    for (int mt = 0; mt < 2; ++mt)
#pragma unroll
        for (int rt = 0; rt < 2; ++rt) {
            int m = m0 + mq * 32 + mt * 16 + er + rt * 8;
            int b = m >> 9, s = m & 511;
            float* orow = g_xin + ((size_t)s * BATCH + b) * HIDDEN + n0;
#pragma unroll
            for (int j = 0; j < 8; ++j) {
                int nl = nh * 64 + j * 8 + ec;
                float2 v;
                v.x = acc[mt][j][rt * 2 + 0] + bin_s[nl];
                v.y = acc[mt][j][rt * 2 + 1] + bin_s[nl + 1];
                *(float2*)(orow + nl) = v;
            }
        }
}

// ---------------- Scan (byte-identical to R10, proven) ----------------
__device__ __forceinline__ void stage_quad(uint32_t sb, const __nv_bfloat16* hi,
                                           const __nv_bfloat16* lo, int i, int m0, int tid)
{
    uint32_t base = sb + OFF_STAGE + (uint32_t)(i % 3) * 32768u;
#pragma unroll
    for (int u = 0; u < 4; ++u) {
        int g = tid + u * 512;
        int seg = g & 7, row = (g >> 3) & 31, plane = (g >> 8) & 1, kg = g >> 9;
        int c = kg * 4 + i;
        const char* src = (const char*)(plane ? lo : hi)
                        + (size_t)(m0 + row) * 2048 + (size_t)c * 128 + seg * 16;
        cp16(base + kg * 8192 + plane * 4096 + row * 128 + ((seg * 16) ^ ((row & 7) << 4)), src);
    }
}

__device__ __forceinline__ void poll_stage(int mt, int i, unsigned need, int tid)
{
    if (tid < 8) {
        int jt = 8 * (tid >> 1) + 2 * i + (tid & 1);
        unsigned* f = &g_flags[(mt * 32 + jt) * 32];
        while ((int)(acq_load(f) - need) < 0) { }
    }
}

__global__ __launch_bounds__(512, 1) void scan_mma_kernel(
    const float* __restrict__ Wh,  const float* __restrict__ bh,
    const float* __restrict__ tau, const float* __restrict__ Wout,
    const float* __restrict__ bout, float* __restrict__ out)
{
    extern __shared__ __align__(1024) char smem[];
    const uint32_t sb = smem_u32(smem);
    const int tid = threadIdx.x, wid = tid >> 5, lid = tid & 31;
    const int jt = blockIdx.x >> 2, mt_blk = blockIdx.x & 3;
    const int j0 = jt * JW, m0 = mt_blk * MW;
    const int me = (mt_blk * 32 + jt) * 32;
    float* bh_s   = (float*)(smem + OFF_BH);
    float* itau_s = (float*)(smem + OFF_ITAU);
    float* red    = (float*)(smem + OFF_RED);

    if (tid == 0) {
        ((unsigned*)(smem + OFF_GEN0))[0] = *(volatile unsigned*)&g_bar_gen;
        ((unsigned*)(smem + OFF_GEN0))[1] = *(volatile unsigned*)&g_flags[me];
    }
    if (tid < JW) {
        bh_s[tid]   = bh[j0 + tid];
        itau_s[tid] = 1.0f / tau[j0 + tid];
    }

    for (int idx = tid; idx < 1024 * 8; idx += 512) {
        int k = idx >> 3, nq = idx & 7;
        float4 wv = *(const float4*)(Wh + (size_t)k * HIDDEN + j0 + nq * 4);
        float w[4] = {wv.x, wv.y, wv.z, wv.w};
#pragma unroll
        for (int e = 0; e < 4; ++e) {
            int n = nq * 4 + e;
            uint32_t so = (uint32_t)((k >> 6) * 4096 + n * 128)
                        + (uint32_t)((((k & 63) * 2) ^ ((n & 7) << 4)));
            __nv_bfloat16 whi = __float2bfloat16(w[e]);
            *(__nv_bfloat16*)(smem + OFF_WHI + so) = whi;
            *(__nv_bfloat16*)(smem + OFF_WLO + so) =
                __float2bfloat16(w[e] - __bfloat162float(whi));
        }
    }
    for (int idx = tid; idx < MW * JW / 2; idx += 512) {
        int r = idx / (JW / 2), c = idx % (JW / 2);
        size_t o = (size_t)(m0 + r) * HIDDEN + j0 + c * 2;
        *(uint32_t*)(g_hhi[0] + o) = 0u;
        *(uint32_t*)(g_hlo[0] + o) = 0u;
    }
    __syncthreads();
    const unsigned gen0 = ((unsigned*)(smem + OFF_GEN0))[0];
    const unsigned B0   = ((unsigned*)(smem + OFF_GEN0))[1];

    grid_sync(gen0 + 1);

    const int w_mt = wid & 1, w_nh = (wid >> 1) & 1, kg = wid >> 2;
    const int grp = lid >> 3;
    const int a_row  = w_mt * 16 + (lid & 7) + ((grp & 1) << 3);
    const int a_koff = (grp >> 1) << 4;
    const uint32_t a_off = (uint32_t)(a_row * 128);
    const uint32_t a_xor = (uint32_t)((a_row & 7) << 4);
    const int b_nr   = w_nh * 16 + (lid & 7) + ((grp >> 1) << 3);
    const int b_koff = (grp & 1) << 4;
    const uint32_t b_xor = (uint32_t)((b_nr & 7) << 4);
    const int er = lid >> 2, ec = (lid & 3) * 2;
    const int q = w_mt * 2 + w_nh;

    const int orow = tid >> 4, ocp = (tid & 15) * 2;
    const int rw_mt = orow >> 4, rlr = orow & 15, rw_nh = ocp >> 4, rlc = ocp & 15;
    const float obh0 = bh_s[ocp], obh1 = bh_s[ocp + 1];
    const float oit0 = itau_s[ocp], oit1 = itau_s[ocp + 1];
    float2 hreg = make_float2(0.f, 0.f);
    float2 xv = *(const float2*)(g_xin + (size_t)(m0 + orow) * HIDDEN + j0 + ocp);

    for (int t = 0; t < SEQ; ++t) {
        const int cur = t % 3, nx = (t + 1) % 3;
        const __nv_bfloat16* hhi = g_hhi[cur];
        const __nv_bfloat16* hlo = g_hlo[cur];
        const unsigned need = B0 + (unsigned)t;

        float a0[2][4], a1[2][4], a2[2][4];
#pragma unroll
        for (int j = 0; j < 2; ++j)
#pragma unroll
            for (int r = 0; r < 4; ++r) { a0[j][r] = 0.f; a1[j][r] = 0.f; a2[j][r] = 0.f; }

        if (tid < 16) {
            int ii = tid >> 3, u = tid & 7;
            int pjt = 8 * (u >> 1) + 2 * ii + (u & 1);
            unsigned* f = &g_flags[(mt_blk * 32 + pjt) * 32];
            while ((int)(acq_load(f) - need) < 0) { }
        }
        __syncthreads();
        stage_quad(sb, hhi, hlo, 0, m0, tid); CP_COMMIT();
        stage_quad(sb, hhi, hlo, 1, m0, tid); CP_COMMIT();

        for (int i = 0; i < 4; ++i) {
            CP_WAIT1();
            __syncthreads();
            if (i + 2 < 4) {
                poll_stage(mt_blk, i + 2, need, tid);
                __syncthreads();
                stage_quad(sb, hhi, hlo, i + 2, m0, tid);
            }
            CP_COMMIT();

            const uint32_t abase = sb + OFF_STAGE + (uint32_t)(i % 3) * 32768u
                                 + (uint32_t)(kg * 8192);
            const uint32_t wbase = sb + OFF_WHI + (uint32_t)((kg * 4 + i) * 4096);
#pragma unroll
            for (int k2 = 0; k2 < 4; ++k2) {
                const uint32_t kb = (uint32_t)(k2 * 32);
                uint32_t ahi[4], alo[4];
                uint32_t aa = abase + a_off + ((kb + a_koff) ^ a_xor);
                ldsm4(ahi[0], ahi[1], ahi[2], ahi[3], aa);
                ldsm4(alo[0], alo[1], alo[2], alo[3], aa + 4096);
                uint32_t bhi[4], blo[4];
                uint32_t ba = wbase + (uint32_t)(b_nr * 128) + ((kb + b_koff) ^ b_xor);
                ldsm4(bhi[0], bhi[1], bhi[2], bhi[3], ba);
                ldsm4(blo[0], blo[1], blo[2], blo[3], ba + (OFF_WLO - OFF_WHI));
#pragma unroll
                for (int j = 0; j < 2; ++j) {
                    mma16816(a0[j], ahi, bhi[j * 2], bhi[j * 2 + 1]);
                    mma16816(a1[j], alo, bhi[j * 2], bhi[j * 2 + 1]);
                    mma16816(a2[j], ahi, blo[j * 2], blo[j * 2 + 1]);
                }
            }
        }
        CP_WAIT0();
        __syncthreads();

        if (wid == 0) {
            unsigned* f = &g_flags[(mt_blk * 32 + lid) * 32];
            while ((int)(acq_load(f) - (need - 1)) < 0) { }
        }
#pragma unroll
        for (int rt = 0; rt < 2; ++rt)
#pragma unroll
            for (int j = 0; j < 2; ++j)
                *(float2*)&red[(kg * 4 + q) * 256 + (rt * 8 + er) * 16 + j * 8 + ec]
                    = make_float2(a0[j][rt * 2] + a1[j][rt * 2] + a2[j][rt * 2],
                                  a0[j][rt * 2 + 1] + a1[j][rt * 2 + 1] + a2[j][rt * 2 + 1]);
        __syncthreads();

        {
            float z0 = xv.x + obh0, z1 = xv.y + obh1;
#pragma unroll
            for (int kg2 = 0; kg2 < 4; ++kg2) {
                float2 pp = *(float2*)&red[(kg2 * 4 + rw_mt * 2 + rw_nh) * 256
                                           + rlr * 16 + rlc];
                z0 += pp.x; z1 += pp.y;
            }
            float d0 = tanhf(z0), d1 = tanhf(z1);
            float h0 = hreg.x + (d0 - hreg.x) * oit0;
            float h1 = hreg.y + (d1 - hreg.y) * oit1;
            hreg = make_float2(h0, h1);
            size_t rb = (size_t)(m0 + orow) * HIDDEN + j0 + ocp;
            __nv_bfloat16 b0 = __float2bfloat16(h0);
            __nv_bfloat16 b1 = __float2bfloat16(h1);
            ((uint32_t*)g_hhi[nx])[rb >> 1] = pbf2(h0, h1);
            ((uint32_t*)g_hlo[nx])[rb >> 1] = pbf2(h0 - __bfloat162float(b0),
                                                   h1 - __bfloat162float(b1));
            if (t == SEQ - 1) *(float2*)(g_hf + rb) = make_float2(h0, h1);
        }

        __syncthreads();
        if (tid == 0) rel_store(&g_flags[me], need + 1);

        {
            int tp = (t + 1 < SEQ) ? t + 1 : t;
            xv = *(const float2*)(g_xin + ((size_t)tp * BATCH + m0 + orow) * HIDDEN + j0 + ocp);
        }
    }

    grid_sync(gen0 + 2);

    if (blockIdx.x < 32) {
        const int b03 = (blockIdx.x >> 3) * 32;
        const int o0  = (blockIdx.x & 7) * 32;
        float* h_s  = (float*)smem;
        float* wo_s = (float*)(smem + OFF_STAGE);
        for (int qq = tid; qq < 32 * 256; qq += 512) {
            int r = qq >> 8, cq = qq & 255;
            float4 v = __ldcg((const float4*)(g_hf + (size_t)(b03 + r) * HIDDEN) + cq);
            *(float4*)&h_s[r * HIDDEN + cq * 4] = v;
        }
        const int ty = tid >> 4, tx = tid & 15;
        float2 acc = *(const float2*)(bout + o0 + tx * 2);
        for (int kc = 0; kc < 16; ++kc) {
            __syncthreads();
            {
                int r = tid >> 3, c4 = tid & 7;
                *(float4*)&wo_s[r * 32 + c4 * 4] =
                    *(const float4*)(Wout + (size_t)(kc * 64 + r) * OUTPUT + o0 + c4 * 4);
            }
            __syncthreads();
#pragma unroll 16
            for (int kk = 0; kk < 64; ++kk) {
                float hvv = h_s[ty * HIDDEN + kc * 64 + kk];
                float2 w = *(const float2*)&wo_s[kk * 32 + tx * 2];
                acc.x += hvv * w.x; acc.y += hvv * w.y;
            }
        }
        *(float2*)(out + (size_t)(b03 + ty) * OUTPUT + o0 + tx * 2) = acc;
    }
}

extern "C" void kernel_launch(void* const* d_in, const int* in_sizes, int n_in,
                              void* d_out, int out_size)
{
    const float* x    = (const float*)d_in[0];
    const float* Win  = (const float*)d_in[1];
    const float* bin  = (const float*)d_in[2];
    const float* Wh   = (const float*)d_in[3];
    const float* bhp  = (const float*)d_in[4];
    const float* tau  = (const float*)d_in[5];
    const float* Wout = (const float*)d_in[6];
    const float* bout = (const float*)d_in[7];
    float* out = (float*)d_out;

    cudaFuncSetAttribute(gemm_xin_mma, cudaFuncAttributeMaxDynamicSharedMemorySize, GEMM_SMEM);
    cudaFuncSetAttribute(scan_mma_kernel, cudaFuncAttributeMaxDynamicSharedMemorySize, SCAN_SMEM);

    conv_x_kernel<<<4096, 256>>>(x);
    conv_w_kernel<<<(INPUT * HIDDEN + 255) / 256, 256>>>(Win);

    dim3 gg(HIDDEN / 128, (BATCH * SEQ) / 128);   // 8 x 512 = 4096 blocks
    gemm_xin_mma<<<gg, 256, GEMM_SMEM>>>(bin);

    scan_mma_kernel<<<NBLK, 512, SCAN_SMEM>>>(Wh, bhp, tau, Wout, bout, out);
}

// round 13
// speedup vs baseline: 1.1037x; 1.0662x over previous
#include <cuda_runtime.h>
#include <cuda_bf16.h>
#include <math.h>
#include <stdint.h>

#define BATCH   128
#define SEQ     512
#define INPUT   512
#define HIDDEN  1024
#define OUTPUT  256
#define NBLK    128
#define JW      32
#define MW      32

__device__ float          g_xin[(size_t)SEQ * BATCH * HIDDEN];
__device__ float          g_hf[BATCH * HIDDEN];
__device__ __nv_bfloat16  g_hhi[3][BATCH * HIDDEN];
__device__ __nv_bfloat16  g_hlo[3][BATCH * HIDDEN];
__device__ __nv_bfloat16  g_xhi[(size_t)BATCH * SEQ * INPUT];
__device__ __nv_bfloat16  g_xlo[(size_t)BATCH * SEQ * INPUT];
__device__ __nv_bfloat16  g_wThi[HIDDEN * INPUT];
__device__ __nv_bfloat16  g_wTlo[HIDDEN * INPUT];
__device__ unsigned g_flags[NBLK * 32];
__device__ unsigned g_bar_cnt;
__device__ unsigned g_bar_gen;

#define OFF_WHI    0
#define OFF_WLO    65536
#define OFF_STAGE  131072
#define OFF_RED    OFF_STAGE
#define OFF_BH     229376
#define OFF_ITAU   229504
#define OFF_GEN0   229632
#define SCAN_SMEM  229696

#define OFF_GA     0
#define OFF_GB     98304
#define OFF_BIN    196608
#define GEMM_SMEM  197120

__device__ __forceinline__ uint32_t smem_u32(const void* p) {
    uint32_t a;
    asm("{ .reg .u64 t; cvta.to.shared.u64 t, %1; cvt.u32.u64 %0, t; }" : "=r"(a) : "l"(p));
    return a;
}
#define CP_COMMIT() asm volatile("cp.async.commit_group;" ::: "memory")
#define CP_WAIT1()  asm volatile("cp.async.wait_group 1;" ::: "memory")

__device__ __forceinline__ void cp16(uint32_t dst, const void* src) {
    asm volatile("cp.async.cg.shared.global [%0], [%1], 16;" :: "r"(dst), "l"(src) : "memory");
}
__device__ __forceinline__ void ldsm4(uint32_t& r0, uint32_t& r1, uint32_t& r2, uint32_t& r3,
                                      uint32_t a) {
    asm volatile("ldmatrix.sync.aligned.m8n8.x4.shared.b16 {%0,%1,%2,%3}, [%4];"
                 : "=r"(r0), "=r"(r1), "=r"(r2), "=r"(r3) : "r"(a));
}
__device__ __forceinline__ void mma16816(float* d, const uint32_t* a, uint32_t b0, uint32_t b1) {
    asm volatile("mma.sync.aligned.m16n8k16.row.col.f32.bf16.bf16.f32 "
                 "{%0,%1,%2,%3}, {%4,%5,%6,%7}, {%8,%9}, {%0,%1,%2,%3};"
                 : "+f"(d[0]), "+f"(d[1]), "+f"(d[2]), "+f"(d[3])
                 : "r"(a[0]), "r"(a[1]), "r"(a[2]), "r"(a[3]), "r"(b0), "r"(b1));
}
__device__ __forceinline__ uint32_t pbf2(float a, float b) {
    __nv_bfloat162 t = __floats2bfloat162_rn(a, b);
    return *(uint32_t*)&t;
}
__device__ __forceinline__ void rel_store(unsigned* p, unsigned v) {
    asm volatile("st.release.gpu.global.u32 [%0], %1;" :: "l"(p), "r"(v) : "memory");
}
__device__ __forceinline__ unsigned acq_load(unsigned* p) {
    unsigned v;
    asm volatile("ld.acquire.gpu.global.u32 %0, [%1];" : "=r"(v) : "l"(p) : "memory");
    return v;
}
__device__ __forceinline__ void grid_sync(unsigned target)
{
    __threadfence();
    __syncthreads();
    if (threadIdx.x == 0) {
        unsigned arrived = atomicAdd(&g_bar_cnt, 1u);
        if (arrived == NBLK - 1) {
            atomicExch(&g_bar_cnt, 0u);
            __threadfence();
            atomicAdd(&g_bar_gen, 1u);
        } else {
            while ((int)(*(volatile unsigned*)&g_bar_gen - target) < 0) { }
            __threadfence();
        }
    }
    __syncthreads();
}

__global__ __launch_bounds__(256) void conv_x_kernel(const float* __restrict__ x)
{
    const size_t total = (size_t)BATCH * SEQ * INPUT / 2;
    size_t base = (size_t)blockIdx.x * 256 + threadIdx.x;
    size_t stride = (size_t)gridDim.x * 256;
    uint32_t* xhi = (uint32_t*)g_xhi;
    uint32_t* xlo = (uint32_t*)g_xlo;
    for (size_t p = base; p < total; p += stride) {
        float2 v = ((const float2*)x)[p];
        uint32_t hp = pbf2(v.x, v.y);
        __nv_bfloat162 hb = *(__nv_bfloat162*)&hp;
        xhi[p] = hp;
        xlo[p] = pbf2(v.x - __bfloat162float(hb.x), v.y - __bfloat162float(hb.y));
    }
}

__global__ __launch_bounds__(256) void conv_w_kernel(const float* __restrict__ Win)
{
    int idx = blockIdx.x * 256 + threadIdx.x;
    if (idx >= INPUT * HIDDEN) return;
    int k = idx >> 10, n = idx & 1023;
    float w = Win[idx];
    __nv_bfloat16 whi = __float2bfloat16(w);
    g_wThi[(size_t)n * INPUT + k] = whi;
    g_wTlo[(size_t)n * INPUT + k] = __float2bfloat16(w - __bfloat162float(whi));
}

// ---------------- Phase 1 GEMM: M=128, N=128, BK=64 ----------------
__device__ __forceinline__ void gstage(uint32_t sb, int kc, int m0, int n0, int tid)
{
    uint32_t abase = sb + OFF_GA + (uint32_t)(kc % 3) * 32768u;
    uint32_t bbase = sb + OFF_GB + (uint32_t)(kc % 3) * 32768u;
#pragma unroll
    for (int u = 0; u < 8; ++u) {
        int g = tid + u * 256;
        int seg = g & 7, row = (g >> 3) & 127, plane = g >> 10;
        const char* src = (const char*)(plane ? g_xlo : g_xhi)
                        + (size_t)(m0 + row) * 1024 + (size_t)kc * 128 + seg * 16;
        cp16(abase + plane * 16384 + row * 128 + ((seg * 16) ^ ((row & 7) << 4)), src);
    }
#pragma unroll
    for (int u = 0; u < 8; ++u) {
        int g = tid + u * 256;
        int seg = g & 7, row = (g >> 3) & 127, plane = g >> 10;
        const char* src = (const char*)(plane ? g_wTlo : g_wThi)
                        + (size_t)(n0 + row) * 1024 + (size_t)kc * 128 + seg * 16;
        cp16(bbase + plane * 16384 + row * 128 + ((seg * 16) ^ ((row & 7) << 4)), src);
    }
}

__global__ __launch_bounds__(256, 1) void gemm_xin_mma(const float* __restrict__ bin)
{
    extern __shared__ __align__(1024) char smem[];
    const uint32_t sb = smem_u32(smem);
    const int tid = threadIdx.x, wid = tid >> 5, lid = tid & 31;
    const int n0 = blockIdx.x * 128, m0 = blockIdx.y * 128;
    const int mq = wid & 3, nh = wid >> 2;
    float* bin_s = (float*)(smem + OFF_BIN);
    if (tid < 32) ((float4*)bin_s)[tid] = ((const float4*)(bin + n0))[tid];

    const int grp = lid >> 3;
    int a_rowl[2];
    a_rowl[0] = mq * 32 + (lid & 7) + ((grp & 1) << 3);
    a_rowl[1] = a_rowl[0] + 16;
    const int a_koff = (grp >> 1) << 4;
    const int b_nr   = nh * 64 + (lid & 7) + ((grp >> 1) << 3);
    const int b_koff = (grp & 1) << 4;
    const uint32_t b_xor = (uint32_t)((b_nr & 7) << 4);

    float acc[2][8][4];
#pragma unroll
    for (int i = 0; i < 2; ++i)
#pragma unroll
        for (int j = 0; j < 8; ++j)
#pragma unroll
            for (int r = 0; r < 4; ++r) acc[i][j][r] = 0.0f;

    gstage(sb, 0, m0, n0, tid); CP_COMMIT();
    gstage(sb, 1, m0, n0, tid); CP_COMMIT();

    for (int kc = 0; kc < 8; ++kc) {
        CP_WAIT1();
        __syncthreads();
        if (kc + 2 < 8) gstage(sb, kc + 2, m0, n0, tid);
        CP_COMMIT();
        const uint32_t abase = sb + OFF_GA + (uint32_t)(kc % 3) * 32768u;
        const uint32_t bbase = sb + OFF_GB + (uint32_t)(kc % 3) * 32768u;
#pragma unroll
        for (int k2 = 0; k2 < 4; ++k2) {
            const uint32_t kb = (uint32_t)(k2 * 32);
            uint32_t ahi[2][4], alo[2][4];
#pragma unroll
            for (int mt = 0; mt < 2; ++mt) {
                uint32_t aa = abase + (uint32_t)(a_rowl[mt] * 128)
                            + ((kb + a_koff) ^ ((a_rowl[mt] & 7) << 4));
                ldsm4(ahi[mt][0], ahi[mt][1], ahi[mt][2], ahi[mt][3], aa);
                ldsm4(alo[mt][0], alo[mt][1], alo[mt][2], alo[mt][3], aa + 16384);
            }
            uint32_t bhi[16], blo[16];
#pragma unroll
            for (int bt = 0; bt < 4; ++bt) {
                uint32_t ba = bbase + (uint32_t)((b_nr + 16 * bt) * 128)
                            + ((kb + b_koff) ^ b_xor);
                ldsm4(bhi[bt * 4 + 0], bhi[bt * 4 + 1], bhi[bt * 4 + 2], bhi[bt * 4 + 3], ba);
                ldsm4(blo[bt * 4 + 0], blo[bt * 4 + 1], blo[bt * 4 + 2], blo[bt * 4 + 3],
                      ba + 16384);
            }
#pragma unroll
            for (int mt = 0; mt < 2; ++mt)
#pragma unroll
                for (int j = 0; j < 8; ++j) {
                    mma16816(acc[mt][j], ahi[mt], bhi[j * 2], bhi[j * 2 + 1]);
                    mma16816(acc[mt][j], alo[mt], bhi[j * 2], bhi[j * 2 + 1]);
                    mma16816(acc[mt][j], ahi[mt], blo[j * 2], blo[j * 2 + 1]);
                }
        }
    }

    const int er = lid >> 2, ec = (lid & 3) * 2;
#pragma unroll
    for (int mt = 0; mt < 2; ++mt)
#pragma unroll
        for (int rt = 0; rt < 2; ++rt) {
            int m = m0 + mq * 32 + mt * 16 + er + rt * 8;
            int b = m >> 9, s = m & 511;
            float* orow = g_xin + ((size_t)s * BATCH + b) * HIDDEN + n0;
#pragma unroll
            for (int j = 0; j < 8; ++j) {
                int nl = nh * 64 + j * 8 + ec;
                float2 v;
                v.x = acc[mt][j][rt * 2 + 0] + bin_s[nl];
                v.y = acc[mt][j][rt * 2 + 1] + bin_s[nl + 1];
                *(float2*)(orow + nl) = v;
            }
        }
}

// ---------------- Scan: 128 blocks x 256 threads, 8 warps = 2m x 4kg ----------------
__device__ __forceinline__ void stage_quad(uint32_t sb, const __nv_bfloat16* hi,
                                           const __nv_bfloat16* lo, int i, int m0, int tid)
{
    uint32_t base = sb + OFF_STAGE + (uint32_t)(i % 3) * 32768u;
#pragma unroll
    for (int u = 0; u < 8; ++u) {
        int g = tid + u * 256;
        int seg = g & 7, row = (g >> 3) & 31, plane = (g >> 8) & 1, kg = g >> 9;
        int c = kg * 4 + i;
        const char* src = (const char*)(plane ? lo : hi)
                        + (size_t)(m0 + row) * 2048 + (size_t)c * 128 + seg * 16;
        cp16(base + kg * 8192 + plane * 4096 + row * 128 + ((seg * 16) ^ ((row & 7) << 4)), src);
    }
}

__device__ __forceinline__ void poll_stage(int mt, int i, unsigned need, int tid)
{
    if (tid < 8) {
        int jt = 8 * (tid >> 1) + 2 * i + (tid & 1);
        unsigned* f = &g_flags[(mt * 32 + jt) * 32];
        while ((int)(acq_load(f) - need) < 0) { }
    }
}

__global__ __launch_bounds__(256, 1) void scan_mma_kernel(
    const float* __restrict__ Wh,  const float* __restrict__ bh,
    const float* __restrict__ tau, const float* __restrict__ Wout,
    const float* __restrict__ bout, float* __restrict__ out)
{
    extern __shared__ __align__(1024) char smem[];
    const uint32_t sb = smem_u32(smem);
    const int tid = threadIdx.x, wid = tid >> 5, lid = tid & 31;
    const int jt = blockIdx.x >> 2, mt_blk = blockIdx.x & 3;
    const int j0 = jt * JW, m0 = mt_blk * MW;
    const int me = (mt_blk * 32 + jt) * 32;
    float* bh_s   = (float*)(smem + OFF_BH);
    float* itau_s = (float*)(smem + OFF_ITAU);
    float* red    = (float*)(smem + OFF_RED);

    if (tid == 0) {
        ((unsigned*)(smem + OFF_GEN0))[0] = *(volatile unsigned*)&g_bar_gen;
        ((unsigned*)(smem + OFF_GEN0))[1] = *(volatile unsigned*)&g_flags[me];
    }
    if (tid < JW) {
        bh_s[tid]   = bh[j0 + tid];
        itau_s[tid] = 1.0f / tau[j0 + tid];
    }

    for (int idx = tid; idx < 1024 * 8; idx += 256) {
        int k = idx >> 3, nq = idx & 7;
        float4 wv = *(const float4*)(Wh + (size_t)k * HIDDEN + j0 + nq * 4);
        float w[4] = {wv.x, wv.y, wv.z, wv.w};
#pragma unroll
        for (int e = 0; e < 4; ++e) {
            int n = nq * 4 + e;
            uint32_t so = (uint32_t)((k >> 6) * 4096 + n * 128)
                        + (uint32_t)((((k & 63) * 2) ^ ((n & 7) << 4)));
            __nv_bfloat16 whi = __float2bfloat16(w[e]);
            *(__nv_bfloat16*)(smem + OFF_WHI + so) = whi;
            *(__nv_bfloat16*)(smem + OFF_WLO + so) =
                __float2bfloat16(w[e] - __bfloat162float(whi));
        }
    }
    for (int idx = tid; idx < MW * JW / 2; idx += 256) {
        int r = idx / (JW / 2), c = idx % (JW / 2);
        size_t o = (size_t)(m0 + r) * HIDDEN + j0 + c * 2;
        *(uint32_t*)(g_hhi[0] + o) = 0u;
        *(uint32_t*)(g_hlo[0] + o) = 0u;
    }
    __syncthreads();
    const unsigned gen0 = ((unsigned*)(smem + OFF_GEN0))[0];
    const unsigned B0   = ((unsigned*)(smem + OFF_GEN0))[1];

    grid_sync(gen0 + 1);

    const int w_m = wid & 1, kg = wid >> 1;
    const int grp = lid >> 3;
    const int a_row  = w_m * 16 + (lid & 7) + ((grp & 1) << 3);
    const int a_koff = (grp >> 1) << 4;
    const uint32_t a_off = (uint32_t)(a_row * 128);
    const uint32_t a_xor = (uint32_t)((a_row & 7) << 4);
    const int b_nr   = (lid & 7) + ((grp >> 1) << 3);
    const int b_koff = (grp & 1) << 4;
    const uint32_t b_xor = (uint32_t)((b_nr & 7) << 4);
    const int er = lid >> 2, ec = (lid & 3) * 2;
    const int slot = kg * 2 + w_m;

    const int orow = tid >> 3, oc4 = (tid & 7) * 4;
    const int emh = orow >> 4, elr = orow & 15;
    const float4 bh4  = *(const float4*)&bh_s[oc4];
    const float4 it4  = *(const float4*)&itau_s[oc4];
    float4 hreg = make_float4(0.f, 0.f, 0.f, 0.f);
    float4 xv = *(const float4*)(g_xin + (size_t)(m0 + orow) * HIDDEN + j0 + oc4);

    uint32_t Bf[8][16];

    for (int t = 0; t < SEQ; ++t) {
        const int cur = t % 3, nx = (t + 1) % 3;
        const __nv_bfloat16* hhi = g_hhi[cur];
        const __nv_bfloat16* hlo = g_hlo[cur];
        const unsigned need = B0 + (unsigned)t;

        float a0[4][4], a1[4][4], a2[4][4];
#pragma unroll
        for (int j = 0; j < 4; ++j)
#pragma unroll
            for (int r = 0; r < 4; ++r) { a0[j][r] = 0.f; a1[j][r] = 0.f; a2[j][r] = 0.f; }

        if (tid < 16) {
            int ii = tid >> 3, u = tid & 7;
            int pjt = 8 * (u >> 1) + 2 * ii + (u & 1);
            unsigned* f = &g_flags[(mt_blk * 32 + pjt) * 32];
            while ((int)(acq_load(f) - need) < 0) { }
        }
        __syncthreads();
        stage_quad(sb, hhi, hlo, 0, m0, tid); CP_COMMIT();
        stage_quad(sb, hhi, hlo, 1, m0, tid); CP_COMMIT();

#pragma unroll
        for (int s2 = 0; s2 < 8; ++s2) {
            int c = kg * 4 + (s2 >> 2);
            uint32_t ba = sb + OFF_WHI + (uint32_t)(c * 4096) + (uint32_t)(b_nr * 128)
                        + (((uint32_t)((s2 & 3) * 32) + b_koff) ^ b_xor);
            ldsm4(Bf[s2][0], Bf[s2][1], Bf[s2][2], Bf[s2][3], ba);
            ldsm4(Bf[s2][4], Bf[s2][5], Bf[s2][6], Bf[s2][7], ba + 2048);
            ldsm4(Bf[s2][8], Bf[s2][9], Bf[s2][10], Bf[s2][11], ba + (OFF_WLO - OFF_WHI));
            ldsm4(Bf[s2][12], Bf[s2][13], Bf[s2][14], Bf[s2][15],
                  ba + (OFF_WLO - OFF_WHI) + 2048);
        }

        for (int i = 0; i < 4; ++i) {
            CP_WAIT1();
            __syncthreads();
            if (i + 2 < 4) {
                poll_stage(mt_blk, i + 2, need, tid);
                __syncthreads();
                stage_quad(sb, hhi, hlo, i + 2, m0, tid);
            }
            CP_COMMIT();

            const uint32_t abase = sb + OFF_STAGE + (uint32_t)(i % 3) * 32768u
                                 + (uint32_t)(kg * 8192);
#pragma unroll
            for (int k2 = 0; k2 < 4; ++k2) {
                const int s2 = (i & 1) * 4 + k2;
                uint32_t ahi[4], alo[4];
                uint32_t aa = abase + a_off + (((uint32_t)(k2 * 32) + a_koff) ^ a_xor);
                ldsm4(ahi[0], ahi[1], ahi[2], ahi[3], aa);
                ldsm4(alo[0], alo[1], alo[2], alo[3], aa + 4096);
#pragma unroll
                for (int j = 0; j < 4; ++j) {
                    mma16816(a0[j], ahi, Bf[s2][j * 2], Bf[s2][j * 2 + 1]);
                    mma16816(a1[j], alo, Bf[s2][j * 2], Bf[s2][j * 2 + 1]);
                    mma16816(a2[j], ahi, Bf[s2][8 + j * 2], Bf[s2][8 + j * 2 + 1]);
                }
            }
            if (i == 1) {
#pragma unroll
                for (int s2 = 0; s2 < 8; ++s2) {
                    int c = kg * 4 + 2 + (s2 >> 2);
                    uint32_t ba = sb + OFF_WHI + (uint32_t)(c * 4096)
                                + (uint32_t)(b_nr * 128)
                                + (((uint32_t)((s2 & 3) * 32) + b_koff) ^ b_xor);
                    ldsm4(Bf[s2][0], Bf[s2][1], Bf[s2][2], Bf[s2][3], ba);
                    ldsm4(Bf[s2][4], Bf[s2][5], Bf[s2][6], Bf[s2][7], ba + 2048);
                    ldsm4(Bf[s2][8], Bf[s2][9], Bf[s2][10], Bf[s2][11],
                          ba + (OFF_WLO - OFF_WHI));
                    ldsm4(Bf[s2][12], Bf[s2][13], Bf[s2][14], Bf[s2][15],
                          ba + (OFF_WLO - OFF_WHI) + 2048);
                }
            }
        }
        __syncthreads();

        if (wid == 0) {
            unsigned* f = &g_flags[(mt_blk * 32 + lid) * 32];
            while ((int)(acq_load(f) - (need - 1)) < 0) { }
        }
#pragma unroll
        for (int rt = 0; rt < 2; ++rt)
#pragma unroll
            for (int j = 0; j < 4; ++j)
                *(float2*)&red[slot * 512 + (rt * 8 + er) * 32 + j * 8 + ec]
                    = make_float2(a0[j][rt * 2] + a1[j][rt * 2] + a2[j][rt * 2],
                                  a0[j][rt * 2 + 1] + a1[j][rt * 2 + 1] + a2[j][rt * 2 + 1]);
        __syncthreads();

        {
            float4 z = make_float4(xv.x + bh4.x, xv.y + bh4.y, xv.z + bh4.z, xv.w + bh4.w);
#pragma unroll
            for (int kg2 = 0; kg2 < 4; ++kg2) {
                float4 pp = *(float4*)&red[(kg2 * 2 + emh) * 512 + elr * 32 + oc4];
                z.x += pp.x; z.y += pp.y; z.z += pp.z; z.w += pp.w;
            }
            float d0 = tanhf(z.x), d1 = tanhf(z.y), d2 = tanhf(z.z), d3 = tanhf(z.w);
            float h0 = hreg.x + (d0 - hreg.x) * it4.x;
            float h1 = hreg.y + (d1 - hreg.y) * it4.y;
            float h2 = hreg.z + (d2 - hreg.z) * it4.z;
            float h3 = hreg.w + (d3 - hreg.w) * it4.w;
            hreg = make_float4(h0, h1, h2, h3);
            size_t rb = (size_t)(m0 + orow) * HIDDEN + j0 + oc4;
            __nv_bfloat16 b0 = __float2bfloat16(h0);
            __nv_bfloat16 b1 = __float2bfloat16(h1);
            __nv_bfloat16 b2 = __float2bfloat16(h2);
            __nv_bfloat16 b3 = __float2bfloat16(h3);
            uint2 vh, vl;
            vh.x = pbf2(h0, h1); vh.y = pbf2(h2, h3);
            vl.x = pbf2(h0 - __bfloat162float(b0), h1 - __bfloat162float(b1));
            vl.y = pbf2(h2 - __bfloat162float(b2), h3 - __bfloat162float(b3));
            *(uint2*)((uint32_t*)g_hhi[nx] + (rb >> 1)) = vh;
            *(uint2*)((uint32_t*)g_hlo[nx] + (rb >> 1)) = vl;
            if (t == SEQ - 1) *(float4*)(g_hf + rb) = make_float4(h0, h1, h2, h3);
        }

        __syncthreads();
        if (tid == 0) rel_store(&g_flags[me], need + 1);

        {
            int tp = (t + 1 < SEQ) ? t + 1 : t;
            xv = *(const float4*)(g_xin + ((size_t)tp * BATCH + m0 + orow) * HIDDEN + j0 + oc4);
        }
    }

    grid_sync(gen0 + 2);

    if (blockIdx.x < 32) {
        const int b03 = (blockIdx.x >> 3) * 32;
        const int o0  = (blockIdx.x & 7) * 32;
        float* h_s  = (float*)smem;
        float* wo_s = (float*)(smem + OFF_STAGE);
        for (int qq = tid; qq < 32 * 256; qq += 256) {
            int r = qq >> 8, cq = qq & 255;
            float4 v = __ldcg((const float4*)(g_hf + (size_t)(b03 + r) * HIDDEN) + cq);
            *(float4*)&h_s[r * HIDDEN + cq * 4] = v;
        }
        const int ty = tid >> 3, tx = tid & 7;
        float4 acc = *(const float4*)(bout + o0 + tx * 4);
        for (int kc = 0; kc < 16; ++kc) {
            __syncthreads();
#pragma unroll
            for (int u = 0; u < 2; ++u) {
                int idx = tid * 2 + u;
                int r = idx >> 3, c4 = idx & 7;
                *(float4*)&wo_s[r * 32 + c4 * 4] =
                    *(const float4*)(Wout + (size_t)(kc * 64 + r) * OUTPUT + o0 + c4 * 4);
            }
            __syncthreads();
#pragma unroll 16
            for (int kk = 0; kk < 64; ++kk) {
                float hvv = h_s[ty * HIDDEN + kc * 64 + kk];
                float4 w = *(const float4*)&wo_s[kk * 32 + tx * 4];
                acc.x += hvv * w.x; acc.y += hvv * w.y;
                acc.z += hvv * w.z; acc.w += hvv * w.w;
            }
        }
        *(float4*)(out + (size_t)(b03 + ty) * OUTPUT + o0 + tx * 4) = acc;
    }
}

extern "C" void kernel_launch(void* const* d_in, const int* in_sizes, int n_in,
                              void* d_out, int out_size)
{
    const float* x    = (const float*)d_in[0];
    const float* Win  = (const float*)d_in[1];
    const float* bin  = (const float*)d_in[2];
    const float* Wh   = (const float*)d_in[3];
    const float* bhp  = (const float*)d_in[4];
    const float* tau  = (const float*)d_in[5];
    const float* Wout = (const float*)d_in[6];
    const float* bout = (const float*)d_in[7];
    float* out = (float*)d_out;

    cudaFuncSetAttribute(gemm_xin_mma, cudaFuncAttributeMaxDynamicSharedMemorySize, GEMM_SMEM);
    cudaFuncSetAttribute(scan_mma_kernel, cudaFuncAttributeMaxDynamicSharedMemorySize, SCAN_SMEM);

    conv_x_kernel<<<4096, 256>>>(x);
    conv_w_kernel<<<(INPUT * HIDDEN + 255) / 256, 256>>>(Win);

    dim3 gg(HIDDEN / 128, (BATCH * SEQ) / 128);
    gemm_xin_mma<<<gg, 256, GEMM_SMEM>>>(bin);

    scan_mma_kernel<<<NBLK, 256, SCAN_SMEM>>>(Wh, bhp, tau, Wout, bout, out);
}

// round 15
// speedup vs baseline: 1.2894x; 1.1683x over previous
#include <cuda_runtime.h>
#include <cuda_bf16.h>
#include <math.h>
#include <stdint.h>

#define BATCH   128
#define SEQ     512
#define INPUT   512
#define HIDDEN  1024
#define OUTPUT  256
#define NBLK    128
#define JW      32
#define MW      32

__device__ float          g_xin[(size_t)SEQ * BATCH * HIDDEN];
__device__ float          g_hf[BATCH * HIDDEN];
__device__ __nv_bfloat16  g_hhi[3][BATCH * HIDDEN];
__device__ __nv_bfloat16  g_hlo[3][BATCH * HIDDEN];
__device__ __nv_bfloat16  g_xhi[(size_t)BATCH * SEQ * INPUT];
__device__ __nv_bfloat16  g_xlo[(size_t)BATCH * SEQ * INPUT];
__device__ __nv_bfloat16  g_wThi[HIDDEN * INPUT];
__device__ __nv_bfloat16  g_wTlo[HIDDEN * INPUT];
__device__ unsigned g_flags[NBLK * 32];
__device__ unsigned g_bar_cnt;
__device__ unsigned g_bar_gen;

#define OFF_WHI    0
#define OFF_WLO    65536
#define OFF_STAGE  131072
#define OFF_RED    OFF_STAGE
#define OFF_BH     229376
#define OFF_ITAU   229504
#define OFF_GEN0   229632
#define SCAN_SMEM  229696

#define OFF_GA     0
#define OFF_GB     98304
#define OFF_BIN    196608
#define GEMM_SMEM  197120

__device__ __forceinline__ uint32_t smem_u32(const void* p) {
    uint32_t a;
    asm("{ .reg .u64 t; cvta.to.shared.u64 t, %1; cvt.u32.u64 %0, t; }" : "=r"(a) : "l"(p));
    return a;
}
#define CP_COMMIT() asm volatile("cp.async.commit_group;" ::: "memory")
#define CP_WAIT2()  asm volatile("cp.async.wait_group 2;" ::: "memory")
#define CP_WAIT1()  asm volatile("cp.async.wait_group 1;" ::: "memory")
#define CP_WAIT0()  asm volatile("cp.async.wait_group 0;" ::: "memory")

__device__ __forceinline__ void cp16(uint32_t dst, const void* src) {
    asm volatile("cp.async.cg.shared.global [%0], [%1], 16;" :: "r"(dst), "l"(src) : "memory");
}
__device__ __forceinline__ void ldsm4(uint32_t& r0, uint32_t& r1, uint32_t& r2, uint32_t& r3,
                                      uint32_t a) {
    asm volatile("ldmatrix.sync.aligned.m8n8.x4.shared.b16 {%0,%1,%2,%3}, [%4];"
                 : "=r"(r0), "=r"(r1), "=r"(r2), "=r"(r3) : "r"(a));
}
__device__ __forceinline__ void mma16816(float* d, const uint32_t* a, uint32_t b0, uint32_t b1) {
    asm volatile("mma.sync.aligned.m16n8k16.row.col.f32.bf16.bf16.f32 "
                 "{%0,%1,%2,%3}, {%4,%5,%6,%7}, {%8,%9}, {%0,%1,%2,%3};"
                 : "+f"(d[0]), "+f"(d[1]), "+f"(d[2]), "+f"(d[3])
                 : "r"(a[0]), "r"(a[1]), "r"(a[2]), "r"(a[3]), "r"(b0), "r"(b1));
}
__device__ __forceinline__ uint32_t pbf2(float a, float b) {
    __nv_bfloat162 t = __floats2bfloat162_rn(a, b);
    return *(uint32_t*)&t;
}
__device__ __forceinline__ void rel_store(unsigned* p, unsigned v) {
    asm volatile("st.release.gpu.global.u32 [%0], %1;" :: "l"(p), "r"(v) : "memory");
}
__device__ __forceinline__ unsigned acq_load(unsigned* p) {
    unsigned v;
    asm volatile("ld.acquire.gpu.global.u32 %0, [%1];" : "=r"(v) : "l"(p) : "memory");
    return v;
}
__device__ __forceinline__ void grid_sync(unsigned target)
{
    __threadfence();
    __syncthreads();
    if (threadIdx.x == 0) {
        unsigned arrived = atomicAdd(&g_bar_cnt, 1u);
        if (arrived == NBLK - 1) {
            atomicExch(&g_bar_cnt, 0u);
            __threadfence();
            atomicAdd(&g_bar_gen, 1u);
        } else {
            while ((int)(*(volatile unsigned*)&g_bar_gen - target) < 0) { }
            __threadfence();
        }
    }
    __syncthreads();
}

__global__ __launch_bounds__(256) void conv_x_kernel(const float* __restrict__ x)
{
    const size_t total = (size_t)BATCH * SEQ * INPUT / 2;
    size_t base = (size_t)blockIdx.x * 256 + threadIdx.x;
    size_t stride = (size_t)gridDim.x * 256;
    uint32_t* xhi = (uint32_t*)g_xhi;
    uint32_t* xlo = (uint32_t*)g_xlo;
    for (size_t p = base; p < total; p += stride) {
        float2 v = ((const float2*)x)[p];
        uint32_t hp = pbf2(v.x, v.y);
        __nv_bfloat162 hb = *(__nv_bfloat162*)&hp;
        xhi[p] = hp;
        xlo[p] = pbf2(v.x - __bfloat162float(hb.x), v.y - __bfloat162float(hb.y));
    }
}

__global__ __launch_bounds__(256) void conv_w_kernel(const float* __restrict__ Win)
{
    int idx = blockIdx.x * 256 + threadIdx.x;
    if (idx >= INPUT * HIDDEN) return;
    int k = idx >> 10, n = idx & 1023;
    float w = Win[idx];
    __nv_bfloat16 whi = __float2bfloat16(w);
    g_wThi[(size_t)n * INPUT + k] = whi;
    g_wTlo[(size_t)n * INPUT + k] = __float2bfloat16(w - __bfloat162float(whi));
}

// ---------------- Phase 1 GEMM: M=128, N=128, BK=64 ----------------
__device__ __forceinline__ void gstage(uint32_t sb, int kc, int m0, int n0, int tid)
{
    uint32_t abase = sb + OFF_GA + (uint32_t)(kc % 3) * 32768u;
    uint32_t bbase = sb + OFF_GB + (uint32_t)(kc % 3) * 32768u;
#pragma unroll
    for (int u = 0; u < 8; ++u) {
        int g = tid + u * 256;
        int seg = g & 7, row = (g >> 3) & 127, plane = g >> 10;
        const char* src = (const char*)(plane ? g_xlo : g_xhi)
                        + (size_t)(m0 + row) * 1024 + (size_t)kc * 128 + seg * 16;
        cp16(abase + plane * 16384 + row * 128 + ((seg * 16) ^ ((row & 7) << 4)), src);
    }
#pragma unroll
    for (int u = 0; u < 8; ++u) {
        int g = tid + u * 256;
        int seg = g & 7, row = (g >> 3) & 127, plane = g >> 10;
        const char* src = (const char*)(plane ? g_wTlo : g_wThi)
                        + (size_t)(n0 + row) * 1024 + (size_t)kc * 128 + seg * 16;
        cp16(bbase + plane * 16384 + row * 128 + ((seg * 16) ^ ((row & 7) << 4)), src);
    }
}

__global__ __launch_bounds__(256, 1) void gemm_xin_mma(const float* __restrict__ bin)
{
    extern __shared__ __align__(1024) char smem[];
    const uint32_t sb = smem_u32(smem);
    const int tid = threadIdx.x, wid = tid >> 5, lid = tid & 31;
    const int n0 = blockIdx.x * 128, m0 = blockIdx.y * 128;
    const int mq = wid & 3, nh = wid >> 2;
    float* bin_s = (float*)(smem + OFF_BIN);
    if (tid < 32) ((float4*)bin_s)[tid] = ((const float4*)(bin + n0))[tid];

    const int grp = lid >> 3;
    int a_rowl[2];
    a_rowl[0] = mq * 32 + (lid & 7) + ((grp & 1) << 3);
    a_rowl[1] = a_rowl[0] + 16;
    const int a_koff = (grp >> 1) << 4;
    const int b_nr   = nh * 64 + (lid & 7) + ((grp >> 1) << 3);
    const int b_koff = (grp & 1) << 4;
    const uint32_t b_xor = (uint32_t)((b_nr & 7) << 4);

    float acc[2][8][4];
#pragma unroll
    for (int i = 0; i < 2; ++i)
#pragma unroll
        for (int j = 0; j < 8; ++j)
#pragma unroll
            for (int r = 0; r < 4; ++r) acc[i][j][r] = 0.0f;

    gstage(sb, 0, m0, n0, tid); CP_COMMIT();
    gstage(sb, 1, m0, n0, tid); CP_COMMIT();

    for (int kc = 0; kc < 8; ++kc) {
        CP_WAIT1();
        __syncthreads();
        if (kc + 2 < 8) gstage(sb, kc + 2, m0, n0, tid);
        CP_COMMIT();
        const uint32_t abase = sb + OFF_GA + (uint32_t)(kc % 3) * 32768u;
        const uint32_t bbase = sb + OFF_GB + (uint32_t)(kc % 3) * 32768u;
#pragma unroll
        for (int k2 = 0; k2 < 4; ++k2) {
            const uint32_t kb = (uint32_t)(k2 * 32);
            uint32_t ahi[2][4], alo[2][4];
#pragma unroll
            for (int mt = 0; mt < 2; ++mt) {
                uint32_t aa = abase + (uint32_t)(a_rowl[mt] * 128)
                            + ((kb + a_koff) ^ ((a_rowl[mt] & 7) << 4));
                ldsm4(ahi[mt][0], ahi[mt][1], ahi[mt][2], ahi[mt][3], aa);
                ldsm4(alo[mt][0], alo[mt][1], alo[mt][2], alo[mt][3], aa + 16384);
            }
            uint32_t bhi[16], blo[16];
#pragma unroll
            for (int bt = 0; bt < 4; ++bt) {
                uint32_t ba = bbase + (uint32_t)((b_nr + 16 * bt) * 128)
                            + ((kb + b_koff) ^ b_xor);
                ldsm4(bhi[bt * 4 + 0], bhi[bt * 4 + 1], bhi[bt * 4 + 2], bhi[bt * 4 + 3], ba);
                ldsm4(blo[bt * 4 + 0], blo[bt * 4 + 1], blo[bt * 4 + 2], blo[bt * 4 + 3],
                      ba + 16384);
            }
#pragma unroll
            for (int mt = 0; mt < 2; ++mt)
#pragma unroll
                for (int j = 0; j < 8; ++j) {
                    mma16816(acc[mt][j], ahi[mt], bhi[j * 2], bhi[j * 2 + 1]);
                    mma16816(acc[mt][j], alo[mt], bhi[j * 2], bhi[j * 2 + 1]);
                    mma16816(acc[mt][j], ahi[mt], blo[j * 2], blo[j * 2 + 1]);
                }
        }
    }

    const int er = lid >> 2, ec = (lid & 3) * 2;
#pragma unroll
    for (int mt = 0; mt < 2; ++mt)
#pragma unroll
        for (int rt = 0; rt < 2; ++rt) {
            int m = m0 + mq * 32 + mt * 16 + er + rt * 8;
            int b = m >> 9, s = m & 511;
            float* orow = g_xin + ((size_t)s * BATCH + b) * HIDDEN + n0;
#pragma unroll
            for (int j = 0; j < 8; ++j) {
                int nl = nh * 64 + j * 8 + ec;
                float2 v;
                v.x = acc[mt][j][rt * 2 + 0] + bin_s[nl];
                v.y = acc[mt][j][rt * 2 + 1] + bin_s[nl + 1];
                *(float2*)(orow + nl) = v;
            }
        }
}

// ---------------- Scan: 128 blocks x 256 threads, 8 warps = 2m x 4kg ----------------
__device__ __forceinline__ void stage_quad(uint32_t sb, const __nv_bfloat16* hi,
                                           const __nv_bfloat16* lo, int i, int m0, int tid)
{
    uint32_t base = sb + OFF_STAGE + (uint32_t)(i % 3) * 32768u;
#pragma unroll
    for (int u = 0; u < 8; ++u) {
        int g = tid + u * 256;
        int seg = g & 7, row = (g >> 3) & 31, plane = (g >> 8) & 1, kg = g >> 9;
        int c = kg * 4 + i;
        const char* src = (const char*)(plane ? lo : hi)
                        + (size_t)(m0 + row) * 2048 + (size_t)c * 128 + seg * 16;
        cp16(base + kg * 8192 + plane * 4096 + row * 128 + ((seg * 16) ^ ((row & 7) << 4)), src);
    }
}

__global__ __launch_bounds__(256, 1) void scan_mma_kernel(
    const float* __restrict__ Wh,  const float* __restrict__ bh,
    const float* __restrict__ tau, const float* __restrict__ Wout,
    const float* __restrict__ bout, float* __restrict__ out)
{
    extern __shared__ __align__(1024) char smem[];
    const uint32_t sb = smem_u32(smem);
    const int tid = threadIdx.x, wid = tid >> 5, lid = tid & 31;
    const int jt = blockIdx.x >> 2, mt_blk = blockIdx.x & 3;
    const int j0 = jt * JW, m0 = mt_blk * MW;
    const int me = (mt_blk * 32 + jt) * 32;
    float* bh_s   = (float*)(smem + OFF_BH);
    float* itau_s = (float*)(smem + OFF_ITAU);
    float* red    = (float*)(smem + OFF_RED);

    if (tid == 0) {
        ((unsigned*)(smem + OFF_GEN0))[0] = *(volatile unsigned*)&g_bar_gen;
        ((unsigned*)(smem + OFF_GEN0))[1] = *(volatile unsigned*)&g_flags[me];
    }
    if (tid < JW) {
        bh_s[tid]   = bh[j0 + tid];
        itau_s[tid] = 1.0f / tau[j0 + tid];
    }

    for (int idx = tid; idx < 1024 * 8; idx += 256) {
        int k = idx >> 3, nq = idx & 7;
        float4 wv = *(const float4*)(Wh + (size_t)k * HIDDEN + j0 + nq * 4);
        float w[4] = {wv.x, wv.y, wv.z, wv.w};
#pragma unroll
        for (int e = 0; e < 4; ++e) {
            int n = nq * 4 + e;
            uint32_t so = (uint32_t)((k >> 6) * 4096 + n * 128)
                        + (uint32_t)((((k & 63) * 2) ^ ((n & 7) << 4)));
            __nv_bfloat16 whi = __float2bfloat16(w[e]);
            *(__nv_bfloat16*)(smem + OFF_WHI + so) = whi;
            *(__nv_bfloat16*)(smem + OFF_WLO + so) =
                __float2bfloat16(w[e] - __bfloat162float(whi));
        }
    }
    for (int idx = tid; idx < MW * JW / 2; idx += 256) {
        int r = idx / (JW / 2), c = idx % (JW / 2);
        size_t o = (size_t)(m0 + r) * HIDDEN + j0 + c * 2;
        *(uint32_t*)(g_hhi[0] + o) = 0u;
        *(uint32_t*)(g_hlo[0] + o) = 0u;
    }
    __syncthreads();
    const unsigned gen0 = ((unsigned*)(smem + OFF_GEN0))[0];
    const unsigned B0   = ((unsigned*)(smem + OFF_GEN0))[1];

    grid_sync(gen0 + 1);

    const int w_m = wid & 1, kg = wid >> 1;
    const int grp = lid >> 3;
    const int a_row  = w_m * 16 + (lid & 7) + ((grp & 1) << 3);
    const int a_koff = (grp >> 1) << 4;
    const uint32_t a_off = (uint32_t)(a_row * 128);
    const uint32_t a_xor = (uint32_t)((a_row & 7) << 4);
    const int b_nr   = (lid & 7) + ((grp >> 1) << 3);
    const int b_koff = (grp & 1) << 4;
    const uint32_t b_xor = (uint32_t)((b_nr & 7) << 4);
    const int er = lid >> 2, ec = (lid & 3) * 2;
    const int slot = kg * 2 + w_m;

    const int orow = tid >> 3, oc4 = (tid & 7) * 4;
    const int emh = orow >> 4, elr = orow & 15;
    const float4 bh4  = *(const float4*)&bh_s[oc4];
    const float4 it4  = *(const float4*)&itau_s[oc4];
    float4 hreg = make_float4(0.f, 0.f, 0.f, 0.f);
    float4 xv = *(const float4*)(g_xin + (size_t)(m0 + orow) * HIDDEN + j0 + oc4);

    uint32_t Bf[8][16];

    for (int t = 0; t < SEQ; ++t) {
        const int cur = t % 3, nx = (t + 1) % 3;
        const __nv_bfloat16* hhi = g_hhi[cur];
        const __nv_bfloat16* hlo = g_hlo[cur];
        const unsigned need = B0 + (unsigned)t;

        float a0[4][4], a1[4][4], a2[4][4];
#pragma unroll
        for (int j = 0; j < 4; ++j)
#pragma unroll
            for (int r = 0; r < 4; ++r) { a0[j][r] = 0.f; a1[j][r] = 0.f; a2[j][r] = 0.f; }

        // single up-front poll of ALL 32 group producers (subsumes clobber guard)
        if (tid < 32) {
            unsigned* f = &g_flags[(mt_blk * 32 + tid) * 32];
            while ((int)(acq_load(f) - need) < 0) { }
        }
        __syncthreads();
        // triple up-front staging
        stage_quad(sb, hhi, hlo, 0, m0, tid); CP_COMMIT();
        stage_quad(sb, hhi, hlo, 1, m0, tid); CP_COMMIT();
        stage_quad(sb, hhi, hlo, 2, m0, tid); CP_COMMIT();

        // B fragments for iterations 0,1 (static W smem)
#pragma unroll
        for (int s2 = 0; s2 < 8; ++s2) {
            int c = kg * 4 + (s2 >> 2);
            uint32_t ba = sb + OFF_WHI + (uint32_t)(c * 4096) + (uint32_t)(b_nr * 128)
                        + (((uint32_t)((s2 & 3) * 32) + b_koff) ^ b_xor);
            ldsm4(Bf[s2][0], Bf[s2][1], Bf[s2][2], Bf[s2][3], ba);
            ldsm4(Bf[s2][4], Bf[s2][5], Bf[s2][6], Bf[s2][7], ba + 2048);
            ldsm4(Bf[s2][8], Bf[s2][9], Bf[s2][10], Bf[s2][11], ba + (OFF_WLO - OFF_WHI));
            ldsm4(Bf[s2][12], Bf[s2][13], Bf[s2][14], Bf[s2][15],
                  ba + (OFF_WLO - OFF_WHI) + 2048);
        }

#pragma unroll
        for (int i = 0; i < 4; ++i) {
            if (i == 0)      CP_WAIT2();
            else if (i == 1) CP_WAIT2();
            else if (i == 2) CP_WAIT1();
            else             CP_WAIT0();
            __syncthreads();

            const uint32_t abase = sb + OFF_STAGE + (uint32_t)(i % 3) * 32768u
                                 + (uint32_t)(kg * 8192);
#pragma unroll
            for (int k2 = 0; k2 < 4; ++k2) {
                const int s2 = (i & 1) * 4 + k2;
                uint32_t ahi[4], alo[4];
                uint32_t aa = abase + a_off + (((uint32_t)(k2 * 32) + a_koff) ^ a_xor);
                ldsm4(ahi[0], ahi[1], ahi[2], ahi[3], aa);
                ldsm4(alo[0], alo[1], alo[2], alo[3], aa + 4096);
#pragma unroll
                for (int j = 0; j < 4; ++j) {
                    mma16816(a0[j], ahi, Bf[s2][j * 2], Bf[s2][j * 2 + 1]);
                    mma16816(a1[j], alo, Bf[s2][j * 2], Bf[s2][j * 2 + 1]);
                    mma16816(a2[j], ahi, Bf[s2][8 + j * 2], Bf[s2][8 + j * 2 + 1]);
                }
            }
            if (i == 0) {
                __syncthreads();
                stage_quad(sb, hhi, hlo, 3, m0, tid);
                CP_COMMIT();
            }
            if (i == 1) {
#pragma unroll
                for (int s2 = 0; s2 < 8; ++s2) {
                    int c = kg * 4 + 2 + (s2 >> 2);
                    uint32_t ba = sb + OFF_WHI + (uint32_t)(c * 4096)
                                + (uint32_t)(b_nr * 128)
                                + (((uint32_t)((s2 & 3) * 32) + b_koff) ^ b_xor);
                    ldsm4(Bf[s2][0], Bf[s2][1], Bf[s2][2], Bf[s2][3], ba);
                    ldsm4(Bf[s2][4], Bf[s2][5], Bf[s2][6], Bf[s2][7], ba + 2048);
                    ldsm4(Bf[s2][8], Bf[s2][9], Bf[s2][10], Bf[s2][11],
                          ba + (OFF_WLO - OFF_WHI));
                    ldsm4(Bf[s2][12], Bf[s2][13], Bf[s2][14], Bf[s2][15],
                          ba + (OFF_WLO - OFF_WHI) + 2048);
                }
            }
        }
        __syncthreads();

        // publish 3-term-summed partials: slot (kg, m-half), [16r][32c]
#pragma unroll
        for (int rt = 0; rt < 2; ++rt)
#pragma unroll
            for (int j = 0; j < 4; ++j)
                *(float2*)&red[slot * 512 + (rt * 8 + er) * 32 + j * 8 + ec]
                    = make_float2(a0[j][rt * 2] + a1[j][rt * 2] + a2[j][rt * 2],
                                  a0[j][rt * 2 + 1] + a1[j][rt * 2 + 1] + a2[j][rt * 2 + 1]);
        __syncthreads();

        // per-thread epilogue: 4 outputs
        {
            float4 z = make_float4(xv.x + bh4.x, xv.y + bh4.y, xv.z + bh4.z, xv.w + bh4.w);
#pragma unroll
            for (int kg2 = 0; kg2 < 4; ++kg2) {
                float4 pp = *(float4*)&red[(kg2 * 2 + emh) * 512 + elr * 32 + oc4];
                z.x += pp.x; z.y += pp.y; z.z += pp.z; z.w += pp.w;
            }
            float d0 = tanhf(z.x), d1 = tanhf(z.y), d2 = tanhf(z.z), d3 = tanhf(z.w);
            float h0 = hreg.x + (d0 - hreg.x) * it4.x;
            float h1 = hreg.y + (d1 - hreg.y) * it4.y;
            float h2 = hreg.z + (d2 - hreg.z) * it4.z;
            float h3 = hreg.w + (d3 - hreg.w) * it4.w;
            hreg = make_float4(h0, h1, h2, h3);
            size_t rb = (size_t)(m0 + orow) * HIDDEN + j0 + oc4;
            __nv_bfloat16 b0 = __float2bfloat16(h0);
            __nv_bfloat16 b1 = __float2bfloat16(h1);
            __nv_bfloat16 b2 = __float2bfloat16(h2);
            __nv_bfloat16 b3 = __float2bfloat16(h3);
            uint2 vh, vl;
            vh.x = pbf2(h0, h1); vh.y = pbf2(h2, h3);
            vl.x = pbf2(h0 - __bfloat162float(b0), h1 - __bfloat162float(b1));
            vl.y = pbf2(h2 - __bfloat162float(b2), h3 - __bfloat162float(b3));
            *(uint2*)((uint32_t*)g_hhi[nx] + (rb >> 1)) = vh;
            *(uint2*)((uint32_t*)g_hlo[nx] + (rb >> 1)) = vl;
            if (t == SEQ - 1) *(float4*)(g_hf + rb) = make_float4(h0, h1, h2, h3);
        }

        __syncthreads();
        if (tid == 0) rel_store(&g_flags[me], need + 1);

        {
            int tp = (t + 1 < SEQ) ? t + 1 : t;
            xv = *(const float4*)(g_xin + ((size_t)tp * BATCH + m0 + orow) * HIDDEN + j0 + oc4);
        }
    }

    grid_sync(gen0 + 2);

    if (blockIdx.x < 32) {
        const int b03 = (blockIdx.x >> 3) * 32;
        const int o0  = (blockIdx.x & 7) * 32;
        float* h_s  = (float*)smem;
        float* wo_s = (float*)(smem + OFF_STAGE);
        for (int qq = tid; qq < 32 * 256; qq += 256) {
            int r = qq >> 8, cq = qq & 255;
            float4 v = __ldcg((const float4*)(g_hf + (size_t)(b03 + r) * HIDDEN) + cq);
            *(float4*)&h_s[r * HIDDEN + cq * 4] = v;
        }
        const int ty = tid >> 3, tx = tid & 7;
        float4 acc = *(const float4*)(bout + o0 + tx * 4);
        for (int kc = 0; kc < 16; ++kc) {
            __syncthreads();
#pragma unroll
            for (int u = 0; u < 2; ++u) {
                int idx = tid * 2 + u;
                int r = idx >> 3, c4 = idx & 7;
                *(float4*)&wo_s[r * 32 + c4 * 4] =
                    *(const float4*)(Wout + (size_t)(kc * 64 + r) * OUTPUT + o0 + c4 * 4);
            }
            __syncthreads();
#pragma unroll 16
            for (int kk = 0; kk < 64; ++kk) {
                float hvv = h_s[ty * HIDDEN + kc * 64 + kk];
                float4 w = *(const float4*)&wo_s[kk * 32 + tx * 4];
                acc.x += hvv * w.x; acc.y += hvv * w.y;
                acc.z += hvv * w.z; acc.w += hvv * w.w;
            }
        }
        *(float4*)(out + (size_t)(b03 + ty) * OUTPUT + o0 + tx * 4) = acc;
    }
}

extern "C" void kernel_launch(void* const* d_in, const int* in_sizes, int n_in,
                              void* d_out, int out_size)
{
    const float* x    = (const float*)d_in[0];
    const float* Win  = (const float*)d_in[1];
    const float* bin  = (const float*)d_in[2];
    const float* Wh   = (const float*)d_in[3];
    const float* bhp  = (const float*)d_in[4];
    const float* tau  = (const float*)d_in[5];
    const float* Wout = (const float*)d_in[6];
    const float* bout = (const float*)d_in[7];
    float* out = (float*)d_out;

    cudaFuncSetAttribute(gemm_xin_mma, cudaFuncAttributeMaxDynamicSharedMemorySize, GEMM_SMEM);
    cudaFuncSetAttribute(scan_mma_kernel, cudaFuncAttributeMaxDynamicSharedMemorySize, SCAN_SMEM);

    conv_x_kernel<<<4096, 256>>>(x);
    conv_w_kernel<<<(INPUT * HIDDEN + 255) / 256, 256>>>(Win);

    dim3 gg(HIDDEN / 128, (BATCH * SEQ) / 128);
    gemm_xin_mma<<<gg, 256, GEMM_SMEM>>>(bin);

    scan_mma_kernel<<<NBLK, 256, SCAN_SMEM>>>(Wh, bhp, tau, Wout, bout, out);
}

// round 16
// speedup vs baseline: 1.3260x; 1.0284x over previous
#include <cuda_runtime.h>
#include <cuda_bf16.h>
#include <math.h>
#include <stdint.h>

#define BATCH   128
#define SEQ     512
#define INPUT   512
#define HIDDEN  1024
#define OUTPUT  256
#define NBLK    128
#define JW      32
#define MW      32

__device__ float          g_xin[(size_t)SEQ * BATCH * HIDDEN];
__device__ float          g_hf[BATCH * HIDDEN];
__device__ __nv_bfloat16  g_hhi[3][BATCH * HIDDEN];
__device__ __nv_bfloat16  g_hlo[3][BATCH * HIDDEN];
__device__ __nv_bfloat16  g_xhi[(size_t)BATCH * SEQ * INPUT];
__device__ __nv_bfloat16  g_xlo[(size_t)BATCH * SEQ * INPUT];
__device__ __nv_bfloat16  g_wThi[HIDDEN * INPUT];
__device__ __nv_bfloat16  g_wTlo[HIDDEN * INPUT];
__device__ unsigned g_flags[NBLK * 32];
__device__ unsigned g_bar_cnt;
__device__ unsigned g_bar_gen;

#define OFF_WHI    0
#define OFF_WLO    65536
#define OFF_STAGE  131072
#define OFF_RED    OFF_STAGE
#define OFF_BH     229376
#define OFF_ITAU   229504
#define OFF_GEN0   229632
#define SCAN_SMEM  229696

#define OFF_GA     0
#define OFF_GB     98304
#define OFF_BIN    196608
#define GEMM_SMEM  197120

__device__ __forceinline__ uint32_t smem_u32(const void* p) {
    uint32_t a;
    asm("{ .reg .u64 t; cvta.to.shared.u64 t, %1; cvt.u32.u64 %0, t; }" : "=r"(a) : "l"(p));
    return a;
}
#define CP_COMMIT() asm volatile("cp.async.commit_group;" ::: "memory")
#define CP_WAIT2()  asm volatile("cp.async.wait_group 2;" ::: "memory")
#define CP_WAIT1()  asm volatile("cp.async.wait_group 1;" ::: "memory")
#define CP_WAIT0()  asm volatile("cp.async.wait_group 0;" ::: "memory")

__device__ __forceinline__ void cp16(uint32_t dst, const void* src) {
    asm volatile("cp.async.cg.shared.global [%0], [%1], 16;" :: "r"(dst), "l"(src) : "memory");
}
__device__ __forceinline__ void ldsm4(uint32_t& r0, uint32_t& r1, uint32_t& r2, uint32_t& r3,
                                      uint32_t a) {
    asm volatile("ldmatrix.sync.aligned.m8n8.x4.shared.b16 {%0,%1,%2,%3}, [%4];"
                 : "=r"(r0), "=r"(r1), "=r"(r2), "=r"(r3) : "r"(a));
}
__device__ __forceinline__ void mma16816(float* d, const uint32_t* a, uint32_t b0, uint32_t b1) {
    asm volatile("mma.sync.aligned.m16n8k16.row.col.f32.bf16.bf16.f32 "
                 "{%0,%1,%2,%3}, {%4,%5,%6,%7}, {%8,%9}, {%0,%1,%2,%3};"
                 : "+f"(d[0]), "+f"(d[1]), "+f"(d[2]), "+f"(d[3])
                 : "r"(a[0]), "r"(a[1]), "r"(a[2]), "r"(a[3]), "r"(b0), "r"(b1));
}
__device__ __forceinline__ uint32_t pbf2(float a, float b) {
    __nv_bfloat162 t = __floats2bfloat162_rn(a, b);
    return *(uint32_t*)&t;
}
__device__ __forceinline__ void rel_store(unsigned* p, unsigned v) {
    asm volatile("st.release.gpu.global.u32 [%0], %1;" :: "l"(p), "r"(v) : "memory");
}
__device__ __forceinline__ unsigned acq_load(unsigned* p) {
    unsigned v;
    asm volatile("ld.acquire.gpu.global.u32 %0, [%1];" : "=r"(v) : "l"(p) : "memory");
    return v;
}
__device__ __forceinline__ void grid_sync(unsigned target)
{
    __threadfence();
    __syncthreads();
    if (threadIdx.x == 0) {
        unsigned arrived = atomicAdd(&g_bar_cnt, 1u);
        if (arrived == NBLK - 1) {
            atomicExch(&g_bar_cnt, 0u);
            __threadfence();
            atomicAdd(&g_bar_gen, 1u);
        } else {
            while ((int)(*(volatile unsigned*)&g_bar_gen - target) < 0) { }
            __threadfence();
        }
    }
    __syncthreads();
}

__global__ __launch_bounds__(256) void conv_x_kernel(const float* __restrict__ x)
{
    const size_t total = (size_t)BATCH * SEQ * INPUT / 2;
    size_t base = (size_t)blockIdx.x * 256 + threadIdx.x;
    size_t stride = (size_t)gridDim.x * 256;
    uint32_t* xhi = (uint32_t*)g_xhi;
    uint32_t* xlo = (uint32_t*)g_xlo;
    for (size_t p = base; p < total; p += stride) {
        float2 v = ((const float2*)x)[p];
        uint32_t hp = pbf2(v.x, v.y);
        __nv_bfloat162 hb = *(__nv_bfloat162*)&hp;
        xhi[p] = hp;
        xlo[p] = pbf2(v.x - __bfloat162float(hb.x), v.y - __bfloat162float(hb.y));
    }
}

__global__ __launch_bounds__(256) void conv_w_kernel(const float* __restrict__ Win)
{
    int idx = blockIdx.x * 256 + threadIdx.x;
    if (idx >= INPUT * HIDDEN) return;
    int k = idx >> 10, n = idx & 1023;
    float w = Win[idx];
    __nv_bfloat16 whi = __float2bfloat16(w);
    g_wThi[(size_t)n * INPUT + k] = whi;
    g_wTlo[(size_t)n * INPUT + k] = __float2bfloat16(w - __bfloat162float(whi));
}

// ---------------- Phase 1 GEMM: M=128, N=128, BK=64 (unchanged) ----------------
__device__ __forceinline__ void gstage(uint32_t sb, int kc, int m0, int n0, int tid)
{
    uint32_t abase = sb + OFF_GA + (uint32_t)(kc % 3) * 32768u;
    uint32_t bbase = sb + OFF_GB + (uint32_t)(kc % 3) * 32768u;
#pragma unroll
    for (int u = 0; u < 8; ++u) {
        int g = tid + u * 256;
        int seg = g & 7, row = (g >> 3) & 127, plane = g >> 10;
        const char* src = (const char*)(plane ? g_xlo : g_xhi)
                        + (size_t)(m0 + row) * 1024 + (size_t)kc * 128 + seg * 16;
        cp16(abase + plane * 16384 + row * 128 + ((seg * 16) ^ ((row & 7) << 4)), src);
    }
#pragma unroll
    for (int u = 0; u < 8; ++u) {
        int g = tid + u * 256;
        int seg = g & 7, row = (g >> 3) & 127, plane = g >> 10;
        const char* src = (const char*)(plane ? g_wTlo : g_wThi)
                        + (size_t)(n0 + row) * 1024 + (size_t)kc * 128 + seg * 16;
        cp16(bbase + plane * 16384 + row * 128 + ((seg * 16) ^ ((row & 7) << 4)), src);
    }
}

__global__ __launch_bounds__(256, 1) void gemm_xin_mma(const float* __restrict__ bin)
{
    extern __shared__ __align__(1024) char smem[];
    const uint32_t sb = smem_u32(smem);
    const int tid = threadIdx.x, wid = tid >> 5, lid = tid & 31;
    const int n0 = blockIdx.x * 128, m0 = blockIdx.y * 128;
    const int mq = wid & 3, nh = wid >> 2;
    float* bin_s = (float*)(smem + OFF_BIN);
    if (tid < 32) ((float4*)bin_s)[tid] = ((const float4*)(bin + n0))[tid];

    const int grp = lid >> 3;
    int a_rowl[2];
    a_rowl[0] = mq * 32 + (lid & 7) + ((grp & 1) << 3);
    a_rowl[1] = a_rowl[0] + 16;
    const int a_koff = (grp >> 1) << 4;
    const int b_nr   = nh * 64 + (lid & 7) + ((grp >> 1) << 3);
    const int b_koff = (grp & 1) << 4;
    const uint32_t b_xor = (uint32_t)((b_nr & 7) << 4);

    float acc[2][8][4];
#pragma unroll
    for (int i = 0; i < 2; ++i)
#pragma unroll
        for (int j = 0; j < 8; ++j)
#pragma unroll
            for (int r = 0; r < 4; ++r) acc[i][j][r] = 0.0f;

    gstage(sb, 0, m0, n0, tid); CP_COMMIT();
    gstage(sb, 1, m0, n0, tid); CP_COMMIT();

    for (int kc = 0; kc < 8; ++kc) {
        CP_WAIT1();
        __syncthreads();
        if (kc + 2 < 8) gstage(sb, kc + 2, m0, n0, tid);
        CP_COMMIT();
        const uint32_t abase = sb + OFF_GA + (uint32_t)(kc % 3) * 32768u;
        const uint32_t bbase = sb + OFF_GB + (uint32_t)(kc % 3) * 32768u;
#pragma unroll
        for (int k2 = 0; k2 < 4; ++k2) {
            const uint32_t kb = (uint32_t)(k2 * 32);
            uint32_t ahi[2][4], alo[2][4];
#pragma unroll
            for (int mt = 0; mt < 2; ++mt) {
                uint32_t aa = abase + (uint32_t)(a_rowl[mt] * 128)
                            + ((kb + a_koff) ^ ((a_rowl[mt] & 7) << 4));
                ldsm4(ahi[mt][0], ahi[mt][1], ahi[mt][2], ahi[mt][3], aa);
                ldsm4(alo[mt][0], alo[mt][1], alo[mt][2], alo[mt][3], aa + 16384);
            }
            uint32_t bhi[16], blo[16];
#pragma unroll
            for (int bt = 0; bt < 4; ++bt) {
                uint32_t ba = bbase + (uint32_t)((b_nr + 16 * bt) * 128)
                            + ((kb + b_koff) ^ b_xor);
                ldsm4(bhi[bt * 4 + 0], bhi[bt * 4 + 1], bhi[bt * 4 + 2], bhi[bt * 4 + 3], ba);
                ldsm4(blo[bt * 4 + 0], blo[bt * 4 + 1], blo[bt * 4 + 2], blo[bt * 4 + 3],
                      ba + 16384);
            }
#pragma unroll
            for (int mt = 0; mt < 2; ++mt)
#pragma unroll
                for (int j = 0; j < 8; ++j) {
                    mma16816(acc[mt][j], ahi[mt], bhi[j * 2], bhi[j * 2 + 1]);
                    mma16816(acc[mt][j], alo[mt], bhi[j * 2], bhi[j * 2 + 1]);
                    mma16816(acc[mt][j], ahi[mt], blo[j * 2], blo[j * 2 + 1]);
                }
        }
    }

    const int er = lid >> 2, ec = (lid & 3) * 2;
#pragma unroll
    for (int mt = 0; mt < 2; ++mt)
#pragma unroll
        for (int rt = 0; rt < 2; ++rt) {
            int m = m0 + mq * 32 + mt * 16 + er + rt * 8;
            int b = m >> 9, s = m & 511;
            float* orow = g_xin + ((size_t)s * BATCH + b) * HIDDEN + n0;
#pragma unroll
            for (int j = 0; j < 8; ++j) {
                int nl = nh * 64 + j * 8 + ec;
                float2 v;
                v.x = acc[mt][j][rt * 2 + 0] + bin_s[nl];
                v.y = acc[mt][j][rt * 2 + 1] + bin_s[nl + 1];
                *(float2*)(orow + nl) = v;
            }
        }
}

// ---------------- Scan: 128 blocks x 256 threads, 8 warps = 8 kg (k128 each) --------
// slot (32KB): pair-section p(4) x 8KB: [hi 4KB | lo 4KB], rows 32 x 128B,
// row byte 0-63 = kg=2p, 64-127 = kg=2p+1 (k32 sub-chunk of iteration i)
__device__ __forceinline__ void stage_quad(uint32_t sb, const __nv_bfloat16* hi,
                                           const __nv_bfloat16* lo, int i, int m0, int tid)
{
    uint32_t base = sb + OFF_STAGE + (uint32_t)(i % 3) * 32768u;
#pragma unroll
    for (int u = 0; u < 8; ++u) {
        int g = tid + u * 256;
        int seg = g & 7, row = (g >> 3) & 31, plane = (g >> 8) & 1, p = g >> 9;
        int kg = p * 2 + (seg >> 2);
        const char* src = (const char*)(plane ? lo : hi)
                        + (size_t)(m0 + row) * 2048 + (size_t)kg * 256 + (size_t)i * 64
                        + (seg & 3) * 16;
        cp16(base + p * 8192 + plane * 4096 + row * 128 + ((seg * 16) ^ ((row & 7) << 4)), src);
    }
}

__global__ __launch_bounds__(256, 1) void scan_mma_kernel(
    const float* __restrict__ Wh,  const float* __restrict__ bh,
    const float* __restrict__ tau, const float* __restrict__ Wout,
    const float* __restrict__ bout, float* __restrict__ out)
{
    extern __shared__ __align__(1024) char smem[];
    const uint32_t sb = smem_u32(smem);
    const int tid = threadIdx.x, wid = tid >> 5, lid = tid & 31;
    const int jt = blockIdx.x >> 2, mt_blk = blockIdx.x & 3;
    const int j0 = jt * JW, m0 = mt_blk * MW;
    const int me = (mt_blk * 32 + jt) * 32;
    float* bh_s   = (float*)(smem + OFF_BH);
    float* itau_s = (float*)(smem + OFF_ITAU);
    float* red    = (float*)(smem + OFF_RED);     // 8 x [32r x 36f] = 36 KB (slots 0-1)

    if (tid == 0) {
        ((unsigned*)(smem + OFF_GEN0))[0] = *(volatile unsigned*)&g_bar_gen;
        ((unsigned*)(smem + OFF_GEN0))[1] = *(volatile unsigned*)&g_flags[me];
    }
    if (tid < JW) {
        bh_s[tid]   = bh[j0 + tid];
        itau_s[tid] = 1.0f / tau[j0 + tid];
    }

    for (int idx = tid; idx < 1024 * 8; idx += 256) {
        int k = idx >> 3, nq = idx & 7;
        float4 wv = *(const float4*)(Wh + (size_t)k * HIDDEN + j0 + nq * 4);
        float w[4] = {wv.x, wv.y, wv.z, wv.w};
#pragma unroll
        for (int e = 0; e < 4; ++e) {
            int n = nq * 4 + e;
            uint32_t so = (uint32_t)((k >> 6) * 4096 + n * 128)
                        + (uint32_t)((((k & 63) * 2) ^ ((n & 7) << 4)));
            __nv_bfloat16 whi = __float2bfloat16(w[e]);
            *(__nv_bfloat16*)(smem + OFF_WHI + so) = whi;
            *(__nv_bfloat16*)(smem + OFF_WLO + so) =
                __float2bfloat16(w[e] - __bfloat162float(whi));
        }
    }
    for (int idx = tid; idx < MW * JW / 2; idx += 256) {
        int r = idx / (JW / 2), c = idx % (JW / 2);
        size_t o = (size_t)(m0 + r) * HIDDEN + j0 + c * 2;
        *(uint32_t*)(g_hhi[0] + o) = 0u;
        *(uint32_t*)(g_hlo[0] + o) = 0u;
    }
    __syncthreads();
    const unsigned gen0 = ((unsigned*)(smem + OFF_GEN0))[0];
    const unsigned B0   = ((unsigned*)(smem + OFF_GEN0))[1];

    grid_sync(gen0 + 1);

    // warp = kg (0..7), full m32 x n32 over k[kg*128, kg*128+128)
    const int kg = wid;
    const int grp = lid >> 3;
    const int p = kg >> 1;
    const uint32_t segb = (uint32_t)((kg & 1) * 4);
    const int rb = (lid & 7) + ((grp & 1) << 3);         // 0..15
    const uint32_t rx = (uint32_t)((rb & 7) << 4);       // row xor (same for rb, rb+16)
    const uint32_t khalf = (uint32_t)(grp >> 1);         // +16B within kstep
    const int b_nr   = (lid & 7) + ((grp >> 1) << 3);
    const int b_koff = (grp & 1) << 4;
    const uint32_t b_xor = (uint32_t)((b_nr & 7) << 4);
    const int er = lid >> 2, ec = (lid & 3) * 2;

    const int orow = tid >> 3, oc4 = (tid & 7) * 4;
    const float4 bh4  = *(const float4*)&bh_s[oc4];
    const float4 it4  = *(const float4*)&itau_s[oc4];
    float4 hreg = make_float4(0.f, 0.f, 0.f, 0.f);
    float4 xv = *(const float4*)(g_xin + (size_t)(m0 + orow) * HIDDEN + j0 + oc4);

    // B fragments: loaded ONCE (W is static). Bf[ks][0..7]=hi pairs, [8..15]=lo.
    uint32_t Bf[8][16];
#pragma unroll
    for (int ks = 0; ks < 8; ++ks) {
        int c = kg * 2 + (ks >> 2);
        uint32_t ba = sb + OFF_WHI + (uint32_t)(c * 4096) + (uint32_t)(b_nr * 128)
                    + (((uint32_t)((ks & 3) * 32) + b_koff) ^ b_xor);
        ldsm4(Bf[ks][0], Bf[ks][1], Bf[ks][2], Bf[ks][3], ba);
        ldsm4(Bf[ks][4], Bf[ks][5], Bf[ks][6], Bf[ks][7], ba + 2048);
        ldsm4(Bf[ks][8], Bf[ks][9], Bf[ks][10], Bf[ks][11], ba + (OFF_WLO - OFF_WHI));
        ldsm4(Bf[ks][12], Bf[ks][13], Bf[ks][14], Bf[ks][15],
              ba + (OFF_WLO - OFF_WHI) + 2048);
    }

    for (int t = 0; t < SEQ; ++t) {
        const int cur = t % 3, nx = (t + 1) % 3;
        const __nv_bfloat16* hhi = g_hhi[cur];
        const __nv_bfloat16* hlo = g_hlo[cur];
        const unsigned need = B0 + (unsigned)t;

        float acc[2][4][4];
#pragma unroll
        for (int mt = 0; mt < 2; ++mt)
#pragma unroll
            for (int j = 0; j < 4; ++j)
#pragma unroll
                for (int r = 0; r < 4; ++r) acc[mt][j][r] = 0.f;

        if (tid < 32) {
            unsigned* f = &g_flags[(mt_blk * 32 + tid) * 32];
            while ((int)(acq_load(f) - need) < 0) { }
        }
        __syncthreads();
        stage_quad(sb, hhi, hlo, 0, m0, tid); CP_COMMIT();
        stage_quad(sb, hhi, hlo, 1, m0, tid); CP_COMMIT();
        stage_quad(sb, hhi, hlo, 2, m0, tid); CP_COMMIT();

#pragma unroll
        for (int i = 0; i < 4; ++i) {
            if (i == 0)      CP_WAIT2();
            else if (i == 1) CP_WAIT2();
            else if (i == 2) CP_WAIT1();
            else             CP_WAIT0();
            __syncthreads();

            const uint32_t abase = sb + OFF_STAGE + (uint32_t)(i % 3) * 32768u
                                 + (uint32_t)(p * 8192);
#pragma unroll
            for (int ks2 = 0; ks2 < 2; ++ks2) {
                const int ks = i * 2 + ks2;
                const uint32_t sbyte = ((segb + (uint32_t)(ks2 * 2) + khalf) * 16u) ^ rx;
                uint32_t ah[2][4], al[2][4];
                uint32_t a0 = abase + (uint32_t)(rb * 128) + sbyte;
                uint32_t a1 = abase + (uint32_t)((rb + 16) * 128) + sbyte;
                ldsm4(ah[0][0], ah[0][1], ah[0][2], ah[0][3], a0);
                ldsm4(ah[1][0], ah[1][1], ah[1][2], ah[1][3], a1);
                ldsm4(al[0][0], al[0][1], al[0][2], al[0][3], a0 + 4096);
                ldsm4(al[1][0], al[1][1], al[1][2], al[1][3], a1 + 4096);
#pragma unroll
                for (int mt = 0; mt < 2; ++mt)
#pragma unroll
                    for (int j = 0; j < 4; ++j) {
                        mma16816(acc[mt][j], ah[mt], Bf[ks][j * 2], Bf[ks][j * 2 + 1]);
                        mma16816(acc[mt][j], al[mt], Bf[ks][j * 2], Bf[ks][j * 2 + 1]);
                        mma16816(acc[mt][j], ah[mt], Bf[ks][8 + j * 2], Bf[ks][8 + j * 2 + 1]);
                    }
            }
            if (i == 0) {
                __syncthreads();
                stage_quad(sb, hhi, hlo, 3, m0, tid);
                CP_COMMIT();
            }
        }
        __syncthreads();

        // publish per-warp partial m32 x n32 into red[kg] (stride-36 rows)
#pragma unroll
        for (int mt = 0; mt < 2; ++mt)
#pragma unroll
            for (int rt = 0; rt < 2; ++rt)
#pragma unroll
                for (int j = 0; j < 4; ++j)
                    *(float2*)&red[kg * 1152 + (mt * 16 + rt * 8 + er) * 36 + j * 8 + ec]
                        = make_float2(acc[mt][j][rt * 2], acc[mt][j][rt * 2 + 1]);
        __syncthreads();

        // per-thread epilogue: 4 outputs, sum 8 kg partials
        {
            float4 z = make_float4(xv.x + bh4.x, xv.y + bh4.y, xv.z + bh4.z, xv.w + bh4.w);
#pragma unroll
            for (int kg2 = 0; kg2 < 8; ++kg2) {
                float4 pp = *(float4*)&red[kg2 * 1152 + orow * 36 + oc4];
                z.x += pp.x; z.y += pp.y; z.z += pp.z; z.w += pp.w;
            }
            float d0 = tanhf(z.x), d1 = tanhf(z.y), d2 = tanhf(z.z), d3 = tanhf(z.w);
            float h0 = hreg.x + (d0 - hreg.x) * it4.x;
            float h1 = hreg.y + (d1 - hreg.y) * it4.y;
            float h2 = hreg.z + (d2 - hreg.z) * it4.z;
            float h3 = hreg.w + (d3 - hreg.w) * it4.w;
            hreg = make_float4(h0, h1, h2, h3);
            size_t rbb = (size_t)(m0 + orow) * HIDDEN + j0 + oc4;
            __nv_bfloat16 c0 = __float2bfloat16(h0);
            __nv_bfloat16 c1 = __float2bfloat16(h1);
            __nv_bfloat16 c2 = __float2bfloat16(h2);
            __nv_bfloat16 c3 = __float2bfloat16(h3);
            uint2 vh, vl;
            vh.x = pbf2(h0, h1); vh.y = pbf2(h2, h3);
            vl.x = pbf2(h0 - __bfloat162float(c0), h1 - __bfloat162float(c1));
            vl.y = pbf2(h2 - __bfloat162float(c2), h3 - __bfloat162float(c3));
            *(uint2*)((uint32_t*)g_hhi[nx] + (rbb >> 1)) = vh;
            *(uint2*)((uint32_t*)g_hlo[nx] + (rbb >> 1)) = vl;
            if (t == SEQ - 1) *(float4*)(g_hf + rbb) = make_float4(h0, h1, h2, h3);
        }

        __syncthreads();
        if (tid == 0) rel_store(&g_flags[me], need + 1);

        {
            int tp = (t + 1 < SEQ) ? t + 1 : t;
            xv = *(const float4*)(g_xin + ((size_t)tp * BATCH + m0 + orow) * HIDDEN + j0 + oc4);
        }
    }

    grid_sync(gen0 + 2);

    if (blockIdx.x < 32) {
        const int b03 = (blockIdx.x >> 3) * 32;
        const int o0  = (blockIdx.x & 7) * 32;
        float* h_s  = (float*)smem;
        float* wo_s = (float*)(smem + OFF_STAGE);
        for (int qq = tid; qq < 32 * 256; qq += 256) {
            int r = qq >> 8, cq = qq & 255;
            float4 v = __ldcg((const float4*)(g_hf + (size_t)(b03 + r) * HIDDEN) + cq);
            *(float4*)&h_s[r * HIDDEN + cq * 4] = v;
        }
        const int ty = tid >> 3, tx = tid & 7;
        float4 acc = *(const float4*)(bout + o0 + tx * 4);
        for (int kc = 0; kc < 16; ++kc) {
            __syncthreads();
#pragma unroll
            for (int u = 0; u < 2; ++u) {
                int idx = tid * 2 + u;
                int r = idx >> 3, c4 = idx & 7;
                *(float4*)&wo_s[r * 32 + c4 * 4] =
                    *(const float4*)(Wout + (size_t)(kc * 64 + r) * OUTPUT + o0 + c4 * 4);
            }
            __syncthreads();
#pragma unroll 16
            for (int kk = 0; kk < 64; ++kk) {
                float hvv = h_s[ty * HIDDEN + kc * 64 + kk];
                float4 w = *(const float4*)&wo_s[kk * 32 + tx * 4];
                acc.x += hvv * w.x; acc.y += hvv * w.y;
                acc.z += hvv * w.z; acc.w += hvv * w.w;
            }
        }
        *(float4*)(out + (size_t)(b03 + ty) * OUTPUT + o0 + tx * 4) = acc;
    }
}

extern "C" void kernel_launch(void* const* d_in, const int* in_sizes, int n_in,
                              void* d_out, int out_size)
{
    const float* x    = (const float*)d_in[0];
    const float* Win  = (const float*)d_in[1];
    const float* bin  = (const float*)d_in[2];
    const float* Wh   = (const float*)d_in[3];
    const float* bhp  = (const float*)d_in[4];
    const float* tau  = (const float*)d_in[5];
    const float* Wout = (const float*)d_in[6];
    const float* bout = (const float*)d_in[7];
    float* out = (float*)d_out;

    cudaFuncSetAttribute(gemm_xin_mma, cudaFuncAttributeMaxDynamicSharedMemorySize, GEMM_SMEM);
    cudaFuncSetAttribute(scan_mma_kernel, cudaFuncAttributeMaxDynamicSharedMemorySize, SCAN_SMEM);

    conv_x_kernel<<<4096, 256>>>(x);
    conv_w_kernel<<<(INPUT * HIDDEN + 255) / 256, 256>>>(Win);

    dim3 gg(HIDDEN / 128, (BATCH * SEQ) / 128);
    gemm_xin_mma<<<gg, 256, GEMM_SMEM>>>(bin);

    scan_mma_kernel<<<NBLK, 256, SCAN_SMEM>>>(Wh, bhp, tau, Wout, bout, out);
}

// round 17
// speedup vs baseline: 1.3341x; 1.0061x over previous
#include <cuda_runtime.h>
#include <cuda_bf16.h>
#include <math.h>
#include <stdint.h>

#define BATCH   128
#define SEQ     512
#define INPUT   512
#define HIDDEN  1024
#define OUTPUT  256
#define NBLK    128
#define JW      32
#define MW      32

__device__ float          g_xin[(size_t)SEQ * BATCH * HIDDEN];
__device__ float          g_hf[BATCH * HIDDEN];
__device__ __nv_bfloat16  g_hhi[3][BATCH * HIDDEN];
__device__ __nv_bfloat16  g_hlo[3][BATCH * HIDDEN];
__device__ __nv_bfloat16  g_xhi[(size_t)BATCH * SEQ * INPUT];
__device__ __nv_bfloat16  g_xlo[(size_t)BATCH * SEQ * INPUT];
__device__ __nv_bfloat16  g_wThi[HIDDEN * INPUT];
__device__ __nv_bfloat16  g_wTlo[HIDDEN * INPUT];
__device__ unsigned g_flags[NBLK * 32];
__device__ unsigned g_bar_cnt;
__device__ unsigned g_bar_gen;

#define OFF_WHI    0
#define OFF_WLO    65536
#define OFF_STAGE  131072
#define OFF_RED    OFF_STAGE
#define OFF_BH     229376
#define OFF_ITAU   229504
#define OFF_GEN0   229632
#define SCAN_SMEM  229696

// gemm: A 2 x 64KB (hi 32K + lo 32K), B 2 x 32KB (hi 16K + lo 16K), bin 512B
#define OFF_GA     0
#define OFF_GB     131072
#define OFF_BIN    196608
#define GEMM_SMEM  197120

__device__ __forceinline__ uint32_t smem_u32(const void* p) {
    uint32_t a;
    asm("{ .reg .u64 t; cvta.to.shared.u64 t, %1; cvt.u32.u64 %0, t; }" : "=r"(a) : "l"(p));
    return a;
}
#define CP_COMMIT() asm volatile("cp.async.commit_group;" ::: "memory")
#define CP_WAIT2()  asm volatile("cp.async.wait_group 2;" ::: "memory")
#define CP_WAIT1()  asm volatile("cp.async.wait_group 1;" ::: "memory")
#define CP_WAIT0()  asm volatile("cp.async.wait_group 0;" ::: "memory")

__device__ __forceinline__ void cp16(uint32_t dst, const void* src) {
    asm volatile("cp.async.cg.shared.global [%0], [%1], 16;" :: "r"(dst), "l"(src) : "memory");
}
__device__ __forceinline__ void ldsm4(uint32_t& r0, uint32_t& r1, uint32_t& r2, uint32_t& r3,
                                      uint32_t a) {
    asm volatile("ldmatrix.sync.aligned.m8n8.x4.shared.b16 {%0,%1,%2,%3}, [%4];"
                 : "=r"(r0), "=r"(r1), "=r"(r2), "=r"(r3) : "r"(a));
}
__device__ __forceinline__ void mma16816(float* d, const uint32_t* a, uint32_t b0, uint32_t b1) {
    asm volatile("mma.sync.aligned.m16n8k16.row.col.f32.bf16.bf16.f32 "
                 "{%0,%1,%2,%3}, {%4,%5,%6,%7}, {%8,%9}, {%0,%1,%2,%3};"
                 : "+f"(d[0]), "+f"(d[1]), "+f"(d[2]), "+f"(d[3])
                 : "r"(a[0]), "r"(a[1]), "r"(a[2]), "r"(a[3]), "r"(b0), "r"(b1));
}
__device__ __forceinline__ uint32_t pbf2(float a, float b) {
    __nv_bfloat162 t = __floats2bfloat162_rn(a, b);
    return *(uint32_t*)&t;
}
__device__ __forceinline__ void rel_store(unsigned* p, unsigned v) {
    asm volatile("st.release.gpu.global.u32 [%0], %1;" :: "l"(p), "r"(v) : "memory");
}
__device__ __forceinline__ unsigned acq_load(unsigned* p) {
    unsigned v;
    asm volatile("ld.acquire.gpu.global.u32 %0, [%1];" : "=r"(v) : "l"(p) : "memory");
    return v;
}
__device__ __forceinline__ void grid_sync(unsigned target)
{
    __threadfence();
    __syncthreads();
    if (threadIdx.x == 0) {
        unsigned arrived = atomicAdd(&g_bar_cnt, 1u);
        if (arrived == NBLK - 1) {
            atomicExch(&g_bar_cnt, 0u);
            __threadfence();
            atomicAdd(&g_bar_gen, 1u);
        } else {
            while ((int)(*(volatile unsigned*)&g_bar_gen - target) < 0) { }
            __threadfence();
        }
    }
    __syncthreads();
}

__global__ __launch_bounds__(256) void conv_x_kernel(const float* __restrict__ x)
{
    const size_t total = (size_t)BATCH * SEQ * INPUT / 2;
    size_t base = (size_t)blockIdx.x * 256 + threadIdx.x;
    size_t stride = (size_t)gridDim.x * 256;
    uint32_t* xhi = (uint32_t*)g_xhi;
    uint32_t* xlo = (uint32_t*)g_xlo;
    for (size_t p = base; p < total; p += stride) {
        float2 v = ((const float2*)x)[p];
        uint32_t hp = pbf2(v.x, v.y);
        __nv_bfloat162 hb = *(__nv_bfloat162*)&hp;
        xhi[p] = hp;
        xlo[p] = pbf2(v.x - __bfloat162float(hb.x), v.y - __bfloat162float(hb.y));
    }
}

__global__ __launch_bounds__(256) void conv_w_kernel(const float* __restrict__ Win)
{
    int idx = blockIdx.x * 256 + threadIdx.x;
    if (idx >= INPUT * HIDDEN) return;
    int k = idx >> 10, n = idx & 1023;
    float w = Win[idx];
    __nv_bfloat16 whi = __float2bfloat16(w);
    g_wThi[(size_t)n * INPUT + k] = whi;
    g_wTlo[(size_t)n * INPUT + k] = __float2bfloat16(w - __bfloat162float(whi));
}

// ---------------- Phase 1 GEMM: M=256, N=128, BK=64, 512 thr, 2-stage ----------------
__device__ __forceinline__ void gstage(uint32_t sb, int kc, int m0, int n0, int tid)
{
    uint32_t abase = sb + OFF_GA + (uint32_t)(kc & 1) * 65536u;
    uint32_t bbase = sb + OFF_GB + (uint32_t)(kc & 1) * 32768u;
#pragma unroll
    for (int u = 0; u < 8; ++u) {                    // A: 4096 cp16 (256 rows, 2 planes)
        int g = tid + u * 512;
        int seg = g & 7, row = (g >> 3) & 255, plane = g >> 11;
        const char* src = (const char*)(plane ? g_xlo : g_xhi)
                        + (size_t)(m0 + row) * 1024 + (size_t)kc * 128 + seg * 16;
        cp16(abase + plane * 32768 + row * 128 + ((seg * 16) ^ ((row & 7) << 4)), src);
    }
#pragma unroll
    for (int u = 0; u < 4; ++u) {                    // B: 2048 cp16 (128 rows, 2 planes)
        int g = tid + u * 512;
        int seg = g & 7, row = (g >> 3) & 127, plane = g >> 10;
        const char* src = (const char*)(plane ? g_wTlo : g_wThi)
                        + (size_t)(n0 + row) * 1024 + (size_t)kc * 128 + seg * 16;
        cp16(bbase + plane * 16384 + row * 128 + ((seg * 16) ^ ((row & 7) << 4)), src);
    }
}

__global__ __launch_bounds__(512, 1) void gemm_xin_mma(const float* __restrict__ bin)
{
    extern __shared__ __align__(1024) char smem[];
    const uint32_t sb = smem_u32(smem);
    const int tid = threadIdx.x, wid = tid >> 5, lid = tid & 31;
    const int n0 = blockIdx.x * 128, m0 = blockIdx.y * 256;
    const int mq = wid & 3, nh = wid >> 2;           // 4 m-warps (m64) x 4 n-warps (n32)
    float* bin_s = (float*)(smem + OFF_BIN);
    if (tid < 32) ((float4*)bin_s)[tid] = ((const float4*)(bin + n0))[tid];

    const int grp = lid >> 3;
    const int a_rbase = mq * 64 + (lid & 7) + ((grp & 1) << 3);   // + mt*16
    const int a_koff  = (grp >> 1) << 4;
    const int b_nr    = nh * 32 + (lid & 7) + ((grp >> 1) << 3);  // + 16 for 2nd x4
    const int b_koff  = (grp & 1) << 4;
    const uint32_t b_xor = (uint32_t)((b_nr & 7) << 4);

    float acc[4][4][4];                              // [mt][j][frag]
#pragma unroll
    for (int mt = 0; mt < 4; ++mt)
#pragma unroll
        for (int j = 0; j < 4; ++j)
#pragma unroll
            for (int r = 0; r < 4; ++r) acc[mt][j][r] = 0.0f;

    gstage(sb, 0, m0, n0, tid); CP_COMMIT();
    gstage(sb, 1, m0, n0, tid); CP_COMMIT();

    for (int kc = 0; kc < 8; ++kc) {
        CP_WAIT1();                                  // chunk kc resident
        __syncthreads();
        const uint32_t abase = sb + OFF_GA + (uint32_t)(kc & 1) * 65536u;
        const uint32_t bbase = sb + OFF_GB + (uint32_t)(kc & 1) * 32768u;
#pragma unroll
        for (int k2 = 0; k2 < 4; ++k2) {
            const uint32_t kb = (uint32_t)(k2 * 32);
            uint32_t bhi[8], blo[8];
            {
                uint32_t ba = bbase + (uint32_t)(b_nr * 128) + ((kb + b_koff) ^ b_xor);
                ldsm4(bhi[0], bhi[1], bhi[2], bhi[3], ba);
                ldsm4(bhi[4], bhi[5], bhi[6], bhi[7], ba + 2048);          // n +16
                ldsm4(blo[0], blo[1], blo[2], blo[3], ba + 16384);
                ldsm4(blo[4], blo[5], blo[6], blo[7], ba + 16384 + 2048);
            }
#pragma unroll
            for (int mt = 0; mt < 4; ++mt) {
                int ar = a_rbase + mt * 16;
                uint32_t aa = abase + (uint32_t)(ar * 128)
                            + ((kb + a_koff) ^ ((ar & 7) << 4));
                uint32_t ahi[4], alo[4];
                ldsm4(ahi[0], ahi[1], ahi[2], ahi[3], aa);
                ldsm4(alo[0], alo[1], alo[2], alo[3], aa + 32768);
#pragma unroll
                for (int j = 0; j < 4; ++j) {
                    mma16816(acc[mt][j], ahi, bhi[j * 2], bhi[j * 2 + 1]);
                    mma16816(acc[mt][j], alo, bhi[j * 2], bhi[j * 2 + 1]);
                    mma16816(acc[mt][j], ahi, blo[j * 2], blo[j * 2 + 1]);
                }
            }
        }
        __syncthreads();                             // all reads of buf kc&1 done
        if (kc + 2 < 8) { gstage(sb, kc + 2, m0, n0, tid); }
        CP_COMMIT();
    }

    const int er = lid >> 2, ec = (lid & 3) * 2;
#pragma unroll
    for (int mt = 0; mt < 4; ++mt)
#pragma unroll
        for (int rt = 0; rt < 2; ++rt) {
            int m = m0 + mq * 64 + mt * 16 + er + rt * 8;
            int b = m >> 9, s = m & 511;
            float* orow = g_xin + ((size_t)s * BATCH + b) * HIDDEN + n0;
#pragma unroll
            for (int j = 0; j < 4; ++j) {
                int nl = nh * 32 + j * 8 + ec;
                float2 v;
                v.x = acc[mt][j][rt * 2 + 0] + bin_s[nl];
                v.y = acc[mt][j][rt * 2 + 1] + bin_s[nl + 1];
                *(float2*)(orow + nl) = v;
            }
        }
}

// ---------------- Scan: byte-identical to R16 (proven, 2.52ms) ----------------
__device__ __forceinline__ void stage_quad(uint32_t sb, const __nv_bfloat16* hi,
                                           const __nv_bfloat16* lo, int i, int m0, int tid)
{
    uint32_t base = sb + OFF_STAGE + (uint32_t)(i % 3) * 32768u;
#pragma unroll
    for (int u = 0; u < 8; ++u) {
        int g = tid + u * 256;
        int seg = g & 7, row = (g >> 3) & 31, plane = (g >> 8) & 1, p = g >> 9;
        int kg = p * 2 + (seg >> 2);
        const char* src = (const char*)(plane ? lo : hi)
                        + (size_t)(m0 + row) * 2048 + (size_t)kg * 256 + (size_t)i * 64
                        + (seg & 3) * 16;
        cp16(base + p * 8192 + plane * 4096 + row * 128 + ((seg * 16) ^ ((row & 7) << 4)), src);
    }
}

__global__ __launch_bounds__(256, 1) void scan_mma_kernel(
    const float* __restrict__ Wh,  const float* __restrict__ bh,
    const float* __restrict__ tau, const float* __restrict__ Wout,
    const float* __restrict__ bout, float* __restrict__ out)
{
    extern __shared__ __align__(1024) char smem[];
    const uint32_t sb = smem_u32(smem);
    const int tid = threadIdx.x, wid = tid >> 5, lid = tid & 31;
    const int jt = blockIdx.x >> 2, mt_blk = blockIdx.x & 3;
    const int j0 = jt * JW, m0 = mt_blk * MW;
    const int me = (mt_blk * 32 + jt) * 32;
    float* bh_s   = (float*)(smem + OFF_BH);
    float* itau_s = (float*)(smem + OFF_ITAU);
    float* red    = (float*)(smem + OFF_RED);

    if (tid == 0) {
        ((unsigned*)(smem + OFF_GEN0))[0] = *(volatile unsigned*)&g_bar_gen;
        ((unsigned*)(smem + OFF_GEN0))[1] = *(volatile unsigned*)&g_flags[me];
    }
    if (tid < JW) {
        bh_s[tid]   = bh[j0 + tid];
        itau_s[tid] = 1.0f / tau[j0 + tid];
    }

    for (int idx = tid; idx < 1024 * 8; idx += 256) {
        int k = idx >> 3, nq = idx & 7;
        float4 wv = *(const float4*)(Wh + (size_t)k * HIDDEN + j0 + nq * 4);
        float w[4] = {wv.x, wv.y, wv.z, wv.w};
#pragma unroll
        for (int e = 0; e < 4; ++e) {
            int n = nq * 4 + e;
            uint32_t so = (uint32_t)((k >> 6) * 4096 + n * 128)
                        + (uint32_t)((((k & 63) * 2) ^ ((n & 7) << 4)));
            __nv_bfloat16 whi = __float2bfloat16(w[e]);
            *(__nv_bfloat16*)(smem + OFF_WHI + so) = whi;
            *(__nv_bfloat16*)(smem + OFF_WLO + so) =
                __float2bfloat16(w[e] - __bfloat162float(whi));
        }
    }
    for (int idx = tid; idx < MW * JW / 2; idx += 256) {
        int r = idx / (JW / 2), c = idx % (JW / 2);
        size_t o = (size_t)(m0 + r) * HIDDEN + j0 + c * 2;
        *(uint32_t*)(g_hhi[0] + o) = 0u;
        *(uint32_t*)(g_hlo[0] + o) = 0u;
    }
    __syncthreads();
    const unsigned gen0 = ((unsigned*)(smem + OFF_GEN0))[0];
    const unsigned B0   = ((unsigned*)(smem + OFF_GEN0))[1];

    grid_sync(gen0 + 1);

    const int kg = wid;
    const int grp = lid >> 3;
    const int p = kg >> 1;
    const uint32_t segb = (uint32_t)((kg & 1) * 4);
    const int rb = (lid & 7) + ((grp & 1) << 3);
    const uint32_t rx = (uint32_t)((rb & 7) << 4);
    const uint32_t khalf = (uint32_t)(grp >> 1);
    const int b_nr   = (lid & 7) + ((grp >> 1) << 3);
    const int b_koff = (grp & 1) << 4;
    const uint32_t b_xor = (uint32_t)((b_nr & 7) << 4);
    const int er = lid >> 2, ec = (lid & 3) * 2;

    const int orow = tid >> 3, oc4 = (tid & 7) * 4;
    const float4 bh4  = *(const float4*)&bh_s[oc4];
    const float4 it4  = *(const float4*)&itau_s[oc4];
    float4 hreg = make_float4(0.f, 0.f, 0.f, 0.f);
    float4 xv = *(const float4*)(g_xin + (size_t)(m0 + orow) * HIDDEN + j0 + oc4);

    uint32_t Bf[8][16];
#pragma unroll
    for (int ks = 0; ks < 8; ++ks) {
        int c = kg * 2 + (ks >> 2);
        uint32_t ba = sb + OFF_WHI + (uint32_t)(c * 4096) + (uint32_t)(b_nr * 128)
                    + (((uint32_t)((ks & 3) * 32) + b_koff) ^ b_xor);
        ldsm4(Bf[ks][0], Bf[ks][1], Bf[ks][2], Bf[ks][3], ba);
        ldsm4(Bf[ks][4], Bf[ks][5], Bf[ks][6], Bf[ks][7], ba + 2048);
        ldsm4(Bf[ks][8], Bf[ks][9], Bf[ks][10], Bf[ks][11], ba + (OFF_WLO - OFF_WHI));
        ldsm4(Bf[ks][12], Bf[ks][13], Bf[ks][14], Bf[ks][15],
              ba + (OFF_WLO - OFF_WHI) + 2048);
    }

    for (int t = 0; t < SEQ; ++t) {
        const int cur = t % 3, nx = (t + 1) % 3;
        const __nv_bfloat16* hhi = g_hhi[cur];
        const __nv_bfloat16* hlo = g_hlo[cur];
        const unsigned need = B0 + (unsigned)t;

        float acc[2][4][4];
#pragma unroll
        for (int mt = 0; mt < 2; ++mt)
#pragma unroll
            for (int j = 0; j < 4; ++j)
#pragma unroll
                for (int r = 0; r < 4; ++r) acc[mt][j][r] = 0.f;

        if (tid < 32) {
            unsigned* f = &g_flags[(mt_blk * 32 + tid) * 32];
            while ((int)(acq_load(f) - need) < 0) { }
        }
        __syncthreads();
        stage_quad(sb, hhi, hlo, 0, m0, tid); CP_COMMIT();
        stage_quad(sb, hhi, hlo, 1, m0, tid); CP_COMMIT();
        stage_quad(sb, hhi, hlo, 2, m0, tid); CP_COMMIT();

#pragma unroll
        for (int i = 0; i < 4; ++i) {
            if (i == 0)      CP_WAIT2();
            else if (i == 1) CP_WAIT2();
            else if (i == 2) CP_WAIT1();
            else             CP_WAIT0();
            __syncthreads();

            const uint32_t abase = sb + OFF_STAGE + (uint32_t)(i % 3) * 32768u
                                 + (uint32_t)(p * 8192);
#pragma unroll
            for (int ks2 = 0; ks2 < 2; ++ks2) {
                const int ks = i * 2 + ks2;
                const uint32_t sbyte = ((segb + (uint32_t)(ks2 * 2) + khalf) * 16u) ^ rx;
                uint32_t ah[2][4], al[2][4];
                uint32_t a0 = abase + (uint32_t)(rb * 128) + sbyte;
                uint32_t a1 = abase + (uint32_t)((rb + 16) * 128) + sbyte;
                ldsm4(ah[0][0], ah[0][1], ah[0][2], ah[0][3], a0);
                ldsm4(ah[1][0], ah[1][1], ah[1][2], ah[1][3], a1);
                ldsm4(al[0][0], al[0][1], al[0][2], al[0][3], a0 + 4096);
                ldsm4(al[1][0], al[1][1], al[1][2], al[1][3], a1 + 4096);
#pragma unroll
                for (int mt = 0; mt < 2; ++mt)
#pragma unroll
                    for (int j = 0; j < 4; ++j) {
                        mma16816(acc[mt][j], ah[mt], Bf[ks][j * 2], Bf[ks][j * 2 + 1]);
                        mma16816(acc[mt][j], al[mt], Bf[ks][j * 2], Bf[ks][j * 2 + 1]);
                        mma16816(acc[mt][j], ah[mt], Bf[ks][8 + j * 2], Bf[ks][8 + j * 2 + 1]);
                    }
            }
            if (i == 0) {
                __syncthreads();
                stage_quad(sb, hhi, hlo, 3, m0, tid);
                CP_COMMIT();
            }
        }
        __syncthreads();

#pragma unroll
        for (int mt = 0; mt < 2; ++mt)
#pragma unroll
            for (int rt = 0; rt < 2; ++rt)
#pragma unroll
                for (int j = 0; j < 4; ++j)
                    *(float2*)&red[kg * 1152 + (mt * 16 + rt * 8 + er) * 36 + j * 8 + ec]
                        = make_float2(acc[mt][j][rt * 2], acc[mt][j][rt * 2 + 1]);
        __syncthreads();

        {
            float4 z = make_float4(xv.x + bh4.x, xv.y + bh4.y, xv.z + bh4.z, xv.w + bh4.w);
#pragma unroll
            for (int kg2 = 0; kg2 < 8; ++kg2) {
                float4 pp = *(float4*)&red[kg2 * 1152 + orow * 36 + oc4];
                z.x += pp.x; z.y += pp.y; z.z += pp.z; z.w += pp.w;
            }
            float d0 = tanhf(z.x), d1 = tanhf(z.y), d2 = tanhf(z.z), d3 = tanhf(z.w);
            float h0 = hreg.x + (d0 - hreg.x) * it4.x;
            float h1 = hreg.y + (d1 - hreg.y) * it4.y;
            float h2 = hreg.z + (d2 - hreg.z) * it4.z;
            float h3 = hreg.w + (d3 - hreg.w) * it4.w;
            hreg = make_float4(h0, h1, h2, h3);
            size_t rbb = (size_t)(m0 + orow) * HIDDEN + j0 + oc4;
            __nv_bfloat16 c0 = __float2bfloat16(h0);
            __nv_bfloat16 c1 = __float2bfloat16(h1);
            __nv_bfloat16 c2 = __float2bfloat16(h2);
            __nv_bfloat16 c3 = __float2bfloat16(h3);
            uint2 vh, vl;
            vh.x = pbf2(h0, h1); vh.y = pbf2(h2, h3);
            vl.x = pbf2(h0 - __bfloat162float(c0), h1 - __bfloat162float(c1));
            vl.y = pbf2(h2 - __bfloat162float(c2), h3 - __bfloat162float(c3));
            *(uint2*)((uint32_t*)g_hhi[nx] + (rbb >> 1)) = vh;
            *(uint2*)((uint32_t*)g_hlo[nx] + (rbb >> 1)) = vl;
            if (t == SEQ - 1) *(float4*)(g_hf + rbb) = make_float4(h0, h1, h2, h3);
        }

        __syncthreads();
        if (tid == 0) rel_store(&g_flags[me], need + 1);

        {
            int tp = (t + 1 < SEQ) ? t + 1 : t;
            xv = *(const float4*)(g_xin + ((size_t)tp * BATCH + m0 + orow) * HIDDEN + j0 + oc4);
        }
    }

    grid_sync(gen0 + 2);

    if (blockIdx.x < 32) {
        const int b03 = (blockIdx.x >> 3) * 32;
        const int o0  = (blockIdx.x & 7) * 32;
        float* h_s  = (float*)smem;
        float* wo_s = (float*)(smem + OFF_STAGE);
        for (int qq = tid; qq < 32 * 256; qq += 256) {
            int r = qq >> 8, cq = qq & 255;
            float4 v = __ldcg((const float4*)(g_hf + (size_t)(b03 + r) * HIDDEN) + cq);
            *(float4*)&h_s[r * HIDDEN + cq * 4] = v;
        }
        const int ty = tid >> 3, tx = tid & 7;
        float4 acc = *(const float4*)(bout + o0 + tx * 4);
        for (int kc = 0; kc < 16; ++kc) {
            __syncthreads();
#pragma unroll
            for (int u = 0; u < 2; ++u) {
                int idx = tid * 2 + u;
                int r = idx >> 3, c4 = idx & 7;
                *(float4*)&wo_s[r * 32 + c4 * 4] =
                    *(const float4*)(Wout + (size_t)(kc * 64 + r) * OUTPUT + o0 + c4 * 4);
            }
            __syncthreads();
#pragma unroll 16
            for (int kk = 0; kk < 64; ++kk) {
                float hvv = h_s[ty * HIDDEN + kc * 64 + kk];
                float4 w = *(const float4*)&wo_s[kk * 32 + tx * 4];
                acc.x += hvv * w.x; acc.y += hvv * w.y;
                acc.z += hvv * w.z; acc.w += hvv * w.w;
            }
        }
        *(float4*)(out + (size_t)(b03 + ty) * OUTPUT + o0 + tx * 4) = acc;
    }
}

extern "C" void kernel_launch(void* const* d_in, const int* in_sizes, int n_in,
                              void* d_out, int out_size)
{
    const float* x    = (const float*)d_in[0];
    const float* Win  = (const float*)d_in[1];
    const float* bin  = (const float*)d_in[2];
    const float* Wh   = (const float*)d_in[3];
    const float* bhp  = (const float*)d_in[4];
    const float* tau  = (const float*)d_in[5];
    const float* Wout = (const float*)d_in[6];
    const float* bout = (const float*)d_in[7];
    float* out = (float*)d_out;

    cudaFuncSetAttribute(gemm_xin_mma, cudaFuncAttributeMaxDynamicSharedMemorySize, GEMM_SMEM);
    cudaFuncSetAttribute(scan_mma_kernel, cudaFuncAttributeMaxDynamicSharedMemorySize, SCAN_SMEM);

    conv_x_kernel<<<4096, 256>>>(x);
    conv_w_kernel<<<(INPUT * HIDDEN + 255) / 256, 256>>>(Win);

    dim3 gg(HIDDEN / 128, (BATCH * SEQ) / 256);   // 8 x 256 = 2048 blocks
    gemm_xin_mma<<<gg, 512, GEMM_SMEM>>>(bin);

    scan_mma_kernel<<<NBLK, 256, SCAN_SMEM>>>(Wh, bhp, tau, Wout, bout, out);
}